// round 1
// baseline (speedup 1.0000x reference)
#include <cuda_runtime.h>
#include <math.h>

#define BN_ 8
#define C_ 256
#define L_ 4096
#define BL_ (BN_*L_)
#define NCH 32
#define CHK 128

// ---------------- scratch (device globals; no allocations allowed) ----------
__device__ float g_h  [BL_*C_];          // LN output (b,l,c)
__device__ float g_uz [BL_*512];         // in_proj output: u = [:256], z = [256:]
__device__ float g_xc [2][BL_*C_];       // conv+silu output, direction space
__device__ float g_dt [2][BL_*C_];       // softplus(dt), direction space
__device__ float g_bc [2][BL_*8];        // Bc[0:4], Cc[4:8] per (b,p)
__device__ float g_cs [2][BN_*NCH*C_*8]; // chunk summaries: aProd[4], hEnd[4]
__device__ float g_h0 [2][BN_*NCH*C_*4]; // corrected chunk initial states
__device__ float g_ys [2][BL_*C_];       // scan outputs, direction space

// ---------------- helpers ----------------------------------------------------
__device__ __forceinline__ void blockReduce2(float &a, float &b, float* sA, float* sB) {
    #pragma unroll
    for (int o = 16; o; o >>= 1) {
        a += __shfl_down_sync(0xffffffffu, a, o);
        b += __shfl_down_sync(0xffffffffu, b, o);
    }
    int w = threadIdx.x >> 5, ln = threadIdx.x & 31;
    if (ln == 0) { sA[w] = a; sB[w] = b; }
    __syncthreads();
    if (threadIdx.x < 32) {
        a = (ln < 8) ? sA[ln] : 0.f;
        b = (ln < 8) ? sB[ln] : 0.f;
        #pragma unroll
        for (int o = 4; o; o >>= 1) {
            a += __shfl_down_sync(0xffffffffu, a, o);
            b += __shfl_down_sync(0xffffffffu, b, o);
        }
        if (ln == 0) { sA[0] = a; sB[0] = b; }
    }
    __syncthreads();
    a = sA[0]; b = sB[0];
    __syncthreads();
}

__device__ __forceinline__ float siluf(float x) { return x / (1.f + __expf(-x)); }

// ---------------- K1: transpose + LayerNorm ----------------------------------
__global__ void ln_kernel(const float* __restrict__ x,
                          const float* __restrict__ w,
                          const float* __restrict__ bia) {
    int bl = blockIdx.x;
    int b = bl >> 12, l = bl & (L_ - 1);
    int c = threadIdx.x;
    float v = x[(size_t)b * C_ * L_ + (size_t)c * L_ + l];
    float a = v, q = v * v;
    __shared__ float sA[8], sB[8];
    blockReduce2(a, q, sA, sB);
    float mu  = a * (1.f / C_);
    float var = q * (1.f / C_) - mu * mu;
    g_h[(size_t)bl * C_ + c] = (v - mu) * rsqrtf(var + 1e-5f) * w[c] + bia[c];
}

// ---------------- K2: fp32 SGEMM  C[m][n] = sum_k A[m,k] * W[n,k] -------------
__global__ void sgemm_tn(const float* __restrict__ A, const float* __restrict__ W,
                         float* __restrict__ C, int M, int N, int K) {
    __shared__ float As[8][128];
    __shared__ float Bs[8][128];
    int tid = threadIdx.x;
    int n0 = blockIdx.x * 128, m0 = blockIdx.y * 128;
    int tx = tid & 15, ty = tid >> 4;
    int lrow = tid >> 1, lk = (tid & 1) * 4;
    const float4* Arow = (const float4*)(A + (size_t)(m0 + lrow) * K);
    const float4* Wrow = (const float4*)(W + (size_t)(n0 + lrow) * K);
    float acc[8][8] = {};
    for (int k0 = 0; k0 < K; k0 += 8) {
        float4 av = Arow[(k0 + lk) >> 2];
        float4 wv = Wrow[(k0 + lk) >> 2];
        As[lk + 0][lrow] = av.x; As[lk + 1][lrow] = av.y;
        As[lk + 2][lrow] = av.z; As[lk + 3][lrow] = av.w;
        Bs[lk + 0][lrow] = wv.x; Bs[lk + 1][lrow] = wv.y;
        Bs[lk + 2][lrow] = wv.z; Bs[lk + 3][lrow] = wv.w;
        __syncthreads();
        #pragma unroll
        for (int k = 0; k < 8; k++) {
            float ra[8], rb[8];
            #pragma unroll
            for (int i = 0; i < 8; i++) ra[i] = As[k][ty * 8 + i];
            #pragma unroll
            for (int j = 0; j < 8; j++) rb[j] = Bs[k][tx * 8 + j];
            #pragma unroll
            for (int i = 0; i < 8; i++)
                #pragma unroll
                for (int j = 0; j < 8; j++)
                    acc[i][j] = fmaf(ra[i], rb[j], acc[i][j]);
        }
        __syncthreads();
    }
    for (int i = 0; i < 8; i++) {
        float* crow = C + (size_t)(m0 + ty * 8 + i) * N + n0 + tx * 8;
        float4 o0 = {acc[i][0], acc[i][1], acc[i][2], acc[i][3]};
        float4 o1 = {acc[i][4], acc[i][5], acc[i][6], acc[i][7]};
        ((float4*)crow)[0] = o0;
        ((float4*)crow)[1] = o1;
    }
}

// ---------------- K3: causal dwconv + silu + x_proj + dt_proj + softplus -----
__global__ void convproj_kernel(
    const float* __restrict__ cw0, const float* __restrict__ cb0,
    const float* __restrict__ xp0, const float* __restrict__ dw0, const float* __restrict__ db0,
    const float* __restrict__ cw1, const float* __restrict__ cb1,
    const float* __restrict__ xp1, const float* __restrict__ dw1, const float* __restrict__ db1) {
    int p = blockIdx.x;
    int b = blockIdx.y >> 1, dir = blockIdx.y & 1;
    const float* cw = dir ? cw1 : cw0;
    const float* cb = dir ? cb1 : cb0;
    const float* xp = dir ? xp1 : xp0;
    const float* dw = dir ? dw1 : dw0;
    const float* db = dir ? db1 : db0;
    int c = threadIdx.x;

    float acc = cb[c];
    #pragma unroll
    for (int k = 0; k < 4; k++) {
        int q = p - 3 + k;
        if (q >= 0) {
            int pos = dir ? (L_ - 1 - q) : q;
            acc = fmaf(cw[k * C_ + c], g_uz[((size_t)(b * L_ + pos)) * 512 + c], acc);
        }
    }
    float xc = siluf(acc);
    __shared__ float sxc[C_];
    __shared__ float sdbl[24];
    sxc[c] = xc;
    g_xc[dir][(size_t)(b * L_ + p) * C_ + c] = xc;
    __syncthreads();

    int w = c >> 5, ln = c & 31;
    #pragma unroll
    for (int oi = 0; oi < 3; oi++) {
        int o = w * 3 + oi;
        float s = 0.f;
        #pragma unroll
        for (int i = 0; i < 8; i++)
            s = fmaf(sxc[ln + 32 * i], xp[o * C_ + ln + 32 * i], s);
        #pragma unroll
        for (int off = 16; off; off >>= 1) s += __shfl_down_sync(0xffffffffu, s, off);
        if (ln == 0) sdbl[o] = s;
    }
    __syncthreads();
    if (c < 8) g_bc[dir][(size_t)(b * L_ + p) * 8 + c] = sdbl[16 + c];

    float val = db[c];
    #pragma unroll
    for (int r = 0; r < 16; r++) val = fmaf(sdbl[r], dw[c * 16 + r], val);
    float dtv = (val > 20.f) ? val : log1pf(__expf(val));
    g_dt[dir][(size_t)(b * L_ + p) * C_ + c] = dtv;
}

// ---------------- K4: scan phase 1 — chunk summaries --------------------------
__global__ void scan1_kernel(const float* __restrict__ Alog0, const float* __restrict__ Alog1) {
    int ch = blockIdx.x;
    int b = blockIdx.y >> 1, dir = blockIdx.y & 1;
    int d = threadIdx.x;
    const float* Alog = dir ? Alog1 : Alog0;
    float Av[4];
    #pragma unroll
    for (int n = 0; n < 4; n++) Av[n] = -__expf(Alog[d * 4 + n]);

    __shared__ float sbc[CHK * 8];
    const float* gbc = g_bc[dir] + (size_t)(b * L_ + ch * CHK) * 8;
    for (int i = d; i < CHK * 8; i += 256) sbc[i] = gbc[i];
    __syncthreads();

    const float* dtp = g_dt[dir] + (size_t)(b * L_ + ch * CHK) * C_ + d;
    const float* up  = g_xc[dir] + (size_t)(b * L_ + ch * CHK) * C_ + d;
    float h[4] = {0, 0, 0, 0}, aP[4] = {1, 1, 1, 1};
    for (int t = 0; t < CHK; t++) {
        float dt = dtp[t * C_], uu = up[t * C_];
        float du = dt * uu;
        #pragma unroll
        for (int n = 0; n < 4; n++) {
            float a = __expf(dt * Av[n]);
            h[n] = fmaf(a, h[n], du * sbc[t * 8 + n]);
            aP[n] *= a;
        }
    }
    float* cs = g_cs[dir] + ((size_t)(b * NCH + ch) * C_ + d) * 8;
    #pragma unroll
    for (int n = 0; n < 4; n++) { cs[n] = aP[n]; cs[4 + n] = h[n]; }
}

// ---------------- K5: scan phase 2 — combine chunk states ---------------------
__global__ void scan2_kernel() {
    int b = blockIdx.x >> 1, dir = blockIdx.x & 1;
    int d = threadIdx.x;
    float h[4] = {0, 0, 0, 0};
    for (int ch = 0; ch < NCH; ch++) {
        float* h0 = g_h0[dir] + ((size_t)(b * NCH + ch) * C_ + d) * 4;
        const float* cs = g_cs[dir] + ((size_t)(b * NCH + ch) * C_ + d) * 8;
        #pragma unroll
        for (int n = 0; n < 4; n++) {
            h0[n] = h[n];
            h[n] = fmaf(cs[n], h[n], cs[4 + n]);
        }
    }
}

// ---------------- K6: scan phase 3 — replay with h0, emit y -------------------
__global__ void scan3_kernel(const float* __restrict__ Alog0, const float* __restrict__ Alog1,
                             const float* __restrict__ D0, const float* __restrict__ D1) {
    int ch = blockIdx.x;
    int b = blockIdx.y >> 1, dir = blockIdx.y & 1;
    int d = threadIdx.x;
    const float* Alog = dir ? Alog1 : Alog0;
    const float* Dp   = dir ? D1 : D0;
    float Av[4];
    #pragma unroll
    for (int n = 0; n < 4; n++) Av[n] = -__expf(Alog[d * 4 + n]);
    float Dv = Dp[d];

    __shared__ float sbc[CHK * 8];
    const float* gbc = g_bc[dir] + (size_t)(b * L_ + ch * CHK) * 8;
    for (int i = d; i < CHK * 8; i += 256) sbc[i] = gbc[i];
    __syncthreads();

    const float* h0p = g_h0[dir] + ((size_t)(b * NCH + ch) * C_ + d) * 4;
    float h[4];
    #pragma unroll
    for (int n = 0; n < 4; n++) h[n] = h0p[n];

    const float* dtp = g_dt[dir] + (size_t)(b * L_ + ch * CHK) * C_ + d;
    const float* up  = g_xc[dir] + (size_t)(b * L_ + ch * CHK) * C_ + d;
    float* ysp = g_ys[dir] + (size_t)(b * L_ + ch * CHK) * C_ + d;
    for (int t = 0; t < CHK; t++) {
        float dt = dtp[t * C_], uu = up[t * C_];
        float du = dt * uu;
        float y = uu * Dv;
        #pragma unroll
        for (int n = 0; n < 4; n++) {
            float a = __expf(dt * Av[n]);
            h[n] = fmaf(a, h[n], du * sbc[t * 8 + n]);
            y = fmaf(h[n], sbc[t * 8 + 4 + n], y);
        }
        ysp[t * C_] = y;
    }
}

// ---------------- K7: combine + silu(z) + LN + out_proj + residual ------------
__global__ void final_kernel(const float* __restrict__ x,
                             const float* __restrict__ nw, const float* __restrict__ nb,
                             const float* __restrict__ Wout, float* __restrict__ out) {
    int bl = blockIdx.x;
    int b = bl >> 12, l = bl & (L_ - 1);
    int c = threadIdx.x;
    float yf = g_ys[0][(size_t)bl * C_ + c];
    float yb = g_ys[1][((size_t)(b * L_) + (L_ - 1 - l)) * C_ + c];
    float z  = g_uz[(size_t)bl * 512 + 256 + c];
    float yv = 0.5f * (yf + yb) * siluf(z);

    float a = yv, q = yv * yv;
    __shared__ float sA[8], sB[8];
    blockReduce2(a, q, sA, sB);
    float mu  = a * (1.f / C_);
    float var = q * (1.f / C_) - mu * mu;
    float yn = (yv - mu) * rsqrtf(var + 1e-5f) * nw[c] + nb[c];

    __shared__ float syn[C_];
    syn[c] = yn;
    __syncthreads();

    const float4* wr  = (const float4*)(Wout + (size_t)c * C_);
    const float4* sy4 = (const float4*)syn;
    float a0 = 0.f, a1 = 0.f, a2 = 0.f, a3 = 0.f;
    #pragma unroll
    for (int i = 0; i < 64; i += 4) {
        float4 w0 = wr[i], y0 = sy4[i];
        float4 w1 = wr[i + 1], y1 = sy4[i + 1];
        float4 w2 = wr[i + 2], y2 = sy4[i + 2];
        float4 w3 = wr[i + 3], y3 = sy4[i + 3];
        a0 += w0.x * y0.x + w0.y * y0.y + w0.z * y0.z + w0.w * y0.w;
        a1 += w1.x * y1.x + w1.y * y1.y + w1.z * y1.z + w1.w * y1.w;
        a2 += w2.x * y2.x + w2.y * y2.y + w2.z * y2.z + w2.w * y2.w;
        a3 += w3.x * y3.x + w3.y * y3.y + w3.z * y3.z + w3.w * y3.w;
    }
    float res = (a0 + a1) + (a2 + a3);
    float skip = x[(size_t)b * C_ * L_ + (size_t)c * L_ + l];
    out[(size_t)b * C_ * L_ + (size_t)c * L_ + l] = res + skip;
}

// ---------------- launch ------------------------------------------------------
extern "C" void kernel_launch(void* const* d_in, const int* in_sizes, int n_in,
                              void* d_out, int out_size) {
    const float* x        = (const float*)d_in[0];
    const float* ln_w     = (const float*)d_in[1];
    const float* ln_b     = (const float*)d_in[2];
    const float* in_proj  = (const float*)d_in[3];
    const float* cw_f     = (const float*)d_in[4];
    const float* cb_f     = (const float*)d_in[5];
    const float* xp_f     = (const float*)d_in[6];
    const float* dw_f     = (const float*)d_in[7];
    const float* db_f     = (const float*)d_in[8];
    const float* Alog_f   = (const float*)d_in[9];
    const float* D_f      = (const float*)d_in[10];
    const float* cw_b     = (const float*)d_in[11];
    const float* cb_b     = (const float*)d_in[12];
    const float* xp_b     = (const float*)d_in[13];
    const float* dw_b     = (const float*)d_in[14];
    const float* db_b     = (const float*)d_in[15];
    const float* Alog_b   = (const float*)d_in[16];
    const float* D_b      = (const float*)d_in[17];
    const float* nrm_w    = (const float*)d_in[18];
    const float* nrm_b    = (const float*)d_in[19];
    const float* out_proj = (const float*)d_in[20];
    float* out = (float*)d_out;

    float* gh;  cudaGetSymbolAddress((void**)&gh,  g_h);
    float* guz; cudaGetSymbolAddress((void**)&guz, g_uz);

    // 1. LN
    ln_kernel<<<BL_, 256>>>(x, ln_w, ln_b);
    // 2. in_proj GEMM: (32768 x 512) = h(32768 x 256) * W^T
    sgemm_tn<<<dim3(512 / 128, BL_ / 128), 256>>>(gh, in_proj, guz, BL_, 512, 256);
    // 3. conv + silu + x_proj + dt_proj + softplus (both directions)
    convproj_kernel<<<dim3(L_, BN_ * 2), 256>>>(cw_f, cb_f, xp_f, dw_f, db_f,
                                                cw_b, cb_b, xp_b, dw_b, db_b);
    // 4-6. chunked selective scan
    scan1_kernel<<<dim3(NCH, BN_ * 2), 256>>>(Alog_f, Alog_b);
    scan2_kernel<<<BN_ * 2, 256>>>();
    scan3_kernel<<<dim3(NCH, BN_ * 2), 256>>>(Alog_f, Alog_b, D_f, D_b);
    // 7. combine + LN + out_proj + residual (transposed write)
    final_kernel<<<BL_, 256>>>(x, nrm_w, nrm_b, out_proj, out);
}

// round 2
// speedup vs baseline: 3.5888x; 3.5888x over previous
#include <cuda_runtime.h>
#include <math.h>

#define BN_ 8
#define C_ 256
#define L_ 4096
#define BL_ (BN_*L_)
#define NCH 32
#define CHK 128
#define POS 16

// ---------------- scratch (device globals) -----------------------------------
__device__ float g_h  [BL_*C_];          // LN output / normalized y (reused)
__device__ float g_uz [BL_*512];         // in_proj output: u=[:256], z=[256:]
__device__ float g_xc [2][BL_*C_];       // conv+silu (dir space); [0] reused as out_proj temp
__device__ float g_dt [2][BL_*C_];       // softplus(dt), dir space
__device__ float g_bc [2][BL_*8];        // Bc[0:4], Cc[4:8] per (b,p) dir space
__device__ float g_cs [2][BN_*NCH*C_*8]; // chunk summaries: aProd[4], hEnd[4]
__device__ float g_h0 [2][BN_*NCH*C_*4]; // corrected chunk initial states
__device__ float g_ys [2][BL_*C_];       // scan outputs, ORIGINAL l space (flipped on write)

// ---------------- helpers -----------------------------------------------------
__device__ __forceinline__ float siluf(float x) { return x / (1.f + __expf(-x)); }

__device__ __forceinline__ void blockReduce2(float &a, float &b, float* sA, float* sB) {
    #pragma unroll
    for (int o = 16; o; o >>= 1) {
        a += __shfl_down_sync(0xffffffffu, a, o);
        b += __shfl_down_sync(0xffffffffu, b, o);
    }
    int w = threadIdx.x >> 5, ln = threadIdx.x & 31;
    if (ln == 0) { sA[w] = a; sB[w] = b; }
    __syncthreads();
    if (threadIdx.x < 32) {
        a = (ln < 8) ? sA[ln] : 0.f;
        b = (ln < 8) ? sB[ln] : 0.f;
        #pragma unroll
        for (int o = 4; o; o >>= 1) {
            a += __shfl_down_sync(0xffffffffu, a, o);
            b += __shfl_down_sync(0xffffffffu, b, o);
        }
        if (ln == 0) { sA[0] = a; sB[0] = b; }
    }
    __syncthreads();
    a = sA[0]; b = sB[0];
    __syncthreads();
}

// packed fp32x2 FMA (sm_103a FFMA2)
__device__ __forceinline__ void ffma2(unsigned long long &d, unsigned long long a, unsigned long long b) {
    asm("fma.rn.f32x2 %0, %1, %2, %0;" : "+l"(d) : "l"(a), "l"(b));
}
__device__ __forceinline__ unsigned long long dup2(float x) {
    unsigned long long r;
    unsigned u = __float_as_uint(x);
    asm("mov.b64 %0, {%1, %1};" : "=l"(r) : "r"(u));
    return r;
}

// ---------------- K1: tiled transpose + LayerNorm -----------------------------
__global__ void ln_kernel(const float* __restrict__ x,
                          const float* __restrict__ wgt,
                          const float* __restrict__ bia) {
    __shared__ float s[C_][33];
    __shared__ float smu[32], srs[32];
    int b = blockIdx.x >> 7;          // 128 l-tiles per batch
    int l0 = (blockIdx.x & 127) * 32;
    int tid = threadIdx.x, w = tid >> 5, ln = tid & 31;

    for (int c = w; c < C_; c += 8)
        s[c][ln] = x[((size_t)b * C_ + c) * L_ + l0 + ln];
    __syncthreads();

    // warp w handles l = w*4 .. w*4+3
    #pragma unroll
    for (int j = 0; j < 4; j++) {
        int l = w * 4 + j;
        float sm = 0.f, sq = 0.f;
        #pragma unroll
        for (int i = 0; i < 8; i++) {
            float v = s[ln + 32 * i][l];
            sm += v; sq += v * v;
        }
        #pragma unroll
        for (int o = 16; o; o >>= 1) {
            sm += __shfl_down_sync(0xffffffffu, sm, o);
            sq += __shfl_down_sync(0xffffffffu, sq, o);
        }
        if (ln == 0) {
            float mu = sm * (1.f / C_);
            float var = sq * (1.f / C_) - mu * mu;
            smu[l] = mu; srs[l] = rsqrtf(var + 1e-5f);
        }
    }
    __syncthreads();

    int c = tid;
    float wv = wgt[c], bv = bia[c];
    for (int l = 0; l < 32; l++) {
        float v = s[c][l];
        g_h[((size_t)b * L_ + l0 + l) * C_ + c] = (v - smu[l]) * srs[l] * wv + bv;
    }
}

// ---------------- K2: fp32(x2) SGEMM  C[m][n] = sum_k A[m,k]*W[n,k] ----------
#define TK 16
__global__ void sgemm_tn(const float* __restrict__ A, const float* __restrict__ W,
                         float* __restrict__ C, int M, int N, int K) {
    __shared__ float As[TK][132];
    __shared__ float Bs[TK][132];
    int tid = threadIdx.x;
    int n0 = blockIdx.x * 128, m0 = blockIdx.y * 128;
    int tx = tid & 15, ty = tid >> 4;
    int lrow = tid >> 1, lk = (tid & 1) * 8;
    const float* Ab = A + (size_t)(m0 + lrow) * K + lk;
    const float* Wb = W + (size_t)(n0 + lrow) * K + lk;

    unsigned long long acc2[8][4] = {};

    for (int k0 = 0; k0 < K; k0 += TK) {
        float4 a0 = *(const float4*)(Ab + k0);
        float4 a1 = *(const float4*)(Ab + k0 + 4);
        float4 b0 = *(const float4*)(Wb + k0);
        float4 b1 = *(const float4*)(Wb + k0 + 4);
        As[lk+0][lrow]=a0.x; As[lk+1][lrow]=a0.y; As[lk+2][lrow]=a0.z; As[lk+3][lrow]=a0.w;
        As[lk+4][lrow]=a1.x; As[lk+5][lrow]=a1.y; As[lk+6][lrow]=a1.z; As[lk+7][lrow]=a1.w;
        Bs[lk+0][lrow]=b0.x; Bs[lk+1][lrow]=b0.y; Bs[lk+2][lrow]=b0.z; Bs[lk+3][lrow]=b0.w;
        Bs[lk+4][lrow]=b1.x; Bs[lk+5][lrow]=b1.y; Bs[lk+6][lrow]=b1.z; Bs[lk+7][lrow]=b1.w;
        __syncthreads();
        #pragma unroll
        for (int k = 0; k < TK; k++) {
            float ra[8];
            *(float4*)&ra[0] = *(const float4*)&As[k][ty * 4];
            *(float4*)&ra[4] = *(const float4*)&As[k][64 + ty * 4];
            ulonglong2 p0 = *(const ulonglong2*)&Bs[k][tx * 4];
            ulonglong2 p1 = *(const ulonglong2*)&Bs[k][64 + tx * 4];
            unsigned long long rb[4] = {p0.x, p0.y, p1.x, p1.y};
            #pragma unroll
            for (int i = 0; i < 8; i++) {
                unsigned long long ad = dup2(ra[i]);
                #pragma unroll
                for (int jp = 0; jp < 4; jp++) ffma2(acc2[i][jp], ad, rb[jp]);
            }
        }
        __syncthreads();
    }
    #pragma unroll
    for (int i = 0; i < 8; i++) {
        int row = m0 + ((i < 4) ? (ty * 4 + i) : (64 + ty * 4 + i - 4));
        float* cr = C + (size_t)row * N + n0;
        ulonglong2 s0 = {acc2[i][0], acc2[i][1]};
        ulonglong2 s1 = {acc2[i][2], acc2[i][3]};
        *(ulonglong2*)(cr + tx * 4) = s0;
        *(ulonglong2*)(cr + 64 + tx * 4) = s1;
    }
}

// ---------------- K3: conv + silu + x_proj + dt_proj (16 positions/block) ----
__global__ void convproj_kernel(
    const float* __restrict__ cw0, const float* __restrict__ cb0,
    const float* __restrict__ xp0, const float* __restrict__ dw0, const float* __restrict__ db0,
    const float* __restrict__ cw1, const float* __restrict__ cb1,
    const float* __restrict__ xp1, const float* __restrict__ dw1, const float* __restrict__ db1) {
    extern __shared__ float sh[];
    float* su   = sh;                 // (POS+3) x 256
    float* sxc  = su + (POS + 3) * C_;   // POS x 256
    float* sxpT = sxc + POS * C_;        // 256 x 24 (k-major, out fastest)
    float* sdwT = sxpT + C_ * 24;        // 16 x 256 (rank-major)
    float* sdbl = sdwT + 16 * C_;        // POS x 24

    int ch = blockIdx.x;              // 256 chunks of 16 positions
    int b = blockIdx.y >> 1, dir = blockIdx.y & 1;
    const float* cw = dir ? cw1 : cw0;
    const float* cb = dir ? cb1 : cb0;
    const float* xp = dir ? xp1 : xp0;
    const float* dw = dir ? dw1 : dw0;
    const float* db = dir ? db1 : db0;
    int tid = threadIdx.x;
    int q0 = ch * POS;

    // stage weights (transposed for conflict-free compute reads)
    for (int i = tid; i < 24 * C_; i += 256) {
        int o = i >> 8, k = i & 255;
        sxpT[k * 24 + o] = xp[i];
    }
    for (int i = tid; i < 16 * C_; i += 256) {
        int c = i >> 4, r = i & 15;
        sdwT[r * C_ + c] = dw[i];
    }
    // stage u window: direction positions q0-3 .. q0+15
    for (int i = tid; i < (POS + 3) * C_; i += 256) {
        int j = i >> 8, c = i & 255;
        int q = q0 - 3 + j;
        float v = 0.f;
        if (q >= 0) {
            int phys = dir ? (L_ - 1 - q) : q;
            v = g_uz[((size_t)(b * L_ + phys)) * 512 + c];
        }
        su[j * C_ + c] = v;
    }
    __syncthreads();

    // conv + silu, per thread c over all 16 positions
    {
        int c = tid;
        float w0 = cw[c], w1 = cw[C_ + c], w2 = cw[2 * C_ + c], w3 = cw[3 * C_ + c];
        float cbv = cb[c];
        #pragma unroll
        for (int t = 0; t < POS; t++) {
            float acc = cbv;
            acc = fmaf(w0, su[(t + 0) * C_ + c], acc);
            acc = fmaf(w1, su[(t + 1) * C_ + c], acc);
            acc = fmaf(w2, su[(t + 2) * C_ + c], acc);
            acc = fmaf(w3, su[(t + 3) * C_ + c], acc);
            float xcv = siluf(acc);
            sxc[t * C_ + c] = xcv;
            g_xc[dir][(size_t)(b * L_ + q0 + t) * C_ + c] = xcv;
        }
    }
    __syncthreads();

    // x_dbl mini-GEMM: [16 pos][24] = sxc[16][256] * xpT
    {
        int pos = tid >> 4, o = tid & 15;
        float acc0 = 0.f, acc1 = 0.f;
        const float* xr = sxc + pos * C_;
        for (int k = 0; k < C_; k++) {
            float xv = xr[k];
            acc0 = fmaf(xv, sxpT[k * 24 + o], acc0);
            if (o < 8) acc1 = fmaf(xv, sxpT[k * 24 + 16 + o], acc1);
        }
        sdbl[pos * 24 + o] = acc0;
        if (o < 8) sdbl[pos * 24 + 16 + o] = acc1;
    }
    __syncthreads();

    // write Bc/Cc
    if (tid < POS * 8) {
        int pos = tid >> 3, v = tid & 7;
        g_bc[dir][(size_t)(b * L_ + q0 + pos) * 8 + v] = sdbl[pos * 24 + 16 + v];
    }

    // dt_proj + softplus
    {
        int c = tid;
        float dbv = db[c];
        #pragma unroll
        for (int pos = 0; pos < POS; pos++) {
            float val = dbv;
            #pragma unroll
            for (int r = 0; r < 16; r++)
                val = fmaf(sdbl[pos * 24 + r], sdwT[r * C_ + c], val);
            float dtv = (val > 20.f) ? val : log1pf(__expf(val));
            g_dt[dir][(size_t)(b * L_ + q0 + pos) * C_ + c] = dtv;
        }
    }
}

// ---------------- K4: scan phase 1 — chunk summaries ---------------------------
__global__ void scan1_kernel(const float* __restrict__ Alog0, const float* __restrict__ Alog1) {
    int ch = blockIdx.x;
    int b = blockIdx.y >> 1, dir = blockIdx.y & 1;
    int d = threadIdx.x;
    const float* Alog = dir ? Alog1 : Alog0;
    float Av[4];
    #pragma unroll
    for (int n = 0; n < 4; n++) Av[n] = -__expf(Alog[d * 4 + n]);

    __shared__ float sbc[CHK * 8];
    const float* gbc = g_bc[dir] + (size_t)(b * L_ + ch * CHK) * 8;
    for (int i = d; i < CHK * 8; i += 256) sbc[i] = gbc[i];
    __syncthreads();

    const float* dtp = g_dt[dir] + (size_t)(b * L_ + ch * CHK) * C_ + d;
    const float* up  = g_xc[dir] + (size_t)(b * L_ + ch * CHK) * C_ + d;
    float h[4] = {0, 0, 0, 0}, aP[4] = {1, 1, 1, 1};
    for (int t = 0; t < CHK; t++) {
        float dt = dtp[t * C_], uu = up[t * C_];
        float du = dt * uu;
        #pragma unroll
        for (int n = 0; n < 4; n++) {
            float a = __expf(dt * Av[n]);
            h[n] = fmaf(a, h[n], du * sbc[t * 8 + n]);
            aP[n] *= a;
        }
    }
    float* cs = g_cs[dir] + ((size_t)(b * NCH + ch) * C_ + d) * 8;
    #pragma unroll
    for (int n = 0; n < 4; n++) { cs[n] = aP[n]; cs[4 + n] = h[n]; }
}

// ---------------- K5: scan phase 2 — combine chunk states ----------------------
__global__ void scan2_kernel() {
    int b = blockIdx.x >> 1, dir = blockIdx.x & 1;
    int d = threadIdx.x;
    float h[4] = {0, 0, 0, 0};
    for (int ch = 0; ch < NCH; ch++) {
        float* h0 = g_h0[dir] + ((size_t)(b * NCH + ch) * C_ + d) * 4;
        const float* cs = g_cs[dir] + ((size_t)(b * NCH + ch) * C_ + d) * 8;
        #pragma unroll
        for (int n = 0; n < 4; n++) {
            h0[n] = h[n];
            h[n] = fmaf(cs[n], h[n], cs[4 + n]);
        }
    }
}

// ---------------- K6: scan phase 3 — replay with h0, emit y (flipped) ----------
__global__ void scan3_kernel(const float* __restrict__ Alog0, const float* __restrict__ Alog1,
                             const float* __restrict__ D0, const float* __restrict__ D1) {
    int ch = blockIdx.x;
    int b = blockIdx.y >> 1, dir = blockIdx.y & 1;
    int d = threadIdx.x;
    const float* Alog = dir ? Alog1 : Alog0;
    const float* Dp   = dir ? D1 : D0;
    float Av[4];
    #pragma unroll
    for (int n = 0; n < 4; n++) Av[n] = -__expf(Alog[d * 4 + n]);
    float Dv = Dp[d];

    __shared__ float sbc[CHK * 8];
    const float* gbc = g_bc[dir] + (size_t)(b * L_ + ch * CHK) * 8;
    for (int i = d; i < CHK * 8; i += 256) sbc[i] = gbc[i];
    __syncthreads();

    const float* h0p = g_h0[dir] + ((size_t)(b * NCH + ch) * C_ + d) * 4;
    float h[4];
    #pragma unroll
    for (int n = 0; n < 4; n++) h[n] = h0p[n];

    const float* dtp = g_dt[dir] + (size_t)(b * L_ + ch * CHK) * C_ + d;
    const float* up  = g_xc[dir] + (size_t)(b * L_ + ch * CHK) * C_ + d;
    for (int t = 0; t < CHK; t++) {
        float dt = dtp[t * C_], uu = up[t * C_];
        float du = dt * uu;
        float y = uu * Dv;
        #pragma unroll
        for (int n = 0; n < 4; n++) {
            float a = __expf(dt * Av[n]);
            h[n] = fmaf(a, h[n], du * sbc[t * 8 + n]);
            y = fmaf(h[n], sbc[t * 8 + 4 + n], y);
        }
        int p = ch * CHK + t;
        int l = dir ? (L_ - 1 - p) : p;        // write in original l space
        g_ys[dir][(size_t)(b * L_ + l) * C_ + d] = y;
    }
}

// ---------------- K7: combine + silu(z) + LN -> g_h ----------------------------
__global__ void combine_ln_kernel(const float* __restrict__ nw, const float* __restrict__ nb) {
    int bl = blockIdx.x;
    int c = threadIdx.x;
    float yf = g_ys[0][(size_t)bl * C_ + c];
    float yb = g_ys[1][(size_t)bl * C_ + c];
    float z  = g_uz[(size_t)bl * 512 + 256 + c];
    float yv = 0.5f * (yf + yb) * siluf(z);

    float a = yv, q = yv * yv;
    __shared__ float sA[8], sB[8];
    blockReduce2(a, q, sA, sB);
    float mu  = a * (1.f / C_);
    float var = q * (1.f / C_) - mu * mu;
    g_h[(size_t)bl * C_ + c] = (yv - mu) * rsqrtf(var + 1e-5f) * nw[c] + nb[c];
}

// ---------------- K9: transpose + residual --------------------------------------
__global__ void transres_kernel(const float* __restrict__ tmp, const float* __restrict__ x,
                                float* __restrict__ out) {
    __shared__ float s[32][33];
    int l0 = blockIdx.x * 32;
    int c0 = blockIdx.y * 32;
    int b  = blockIdx.z;
    int tid = threadIdx.x, w = tid >> 5, ln = tid & 31;

    #pragma unroll
    for (int i = w; i < 32; i += 8)
        s[i][ln] = tmp[((size_t)(b * L_ + l0 + i)) * C_ + c0 + ln];
    __syncthreads();
    #pragma unroll
    for (int i = w; i < 32; i += 8) {
        size_t idx = ((size_t)b * C_ + c0 + i) * L_ + l0 + ln;
        out[idx] = s[ln][i] + x[idx];
    }
}

// ---------------- launch ---------------------------------------------------------
extern "C" void kernel_launch(void* const* d_in, const int* in_sizes, int n_in,
                              void* d_out, int out_size) {
    const float* x        = (const float*)d_in[0];
    const float* ln_w     = (const float*)d_in[1];
    const float* ln_b     = (const float*)d_in[2];
    const float* in_proj  = (const float*)d_in[3];
    const float* cw_f     = (const float*)d_in[4];
    const float* cb_f     = (const float*)d_in[5];
    const float* xp_f     = (const float*)d_in[6];
    const float* dw_f     = (const float*)d_in[7];
    const float* db_f     = (const float*)d_in[8];
    const float* Alog_f   = (const float*)d_in[9];
    const float* D_f      = (const float*)d_in[10];
    const float* cw_b     = (const float*)d_in[11];
    const float* cb_b     = (const float*)d_in[12];
    const float* xp_b     = (const float*)d_in[13];
    const float* dw_b     = (const float*)d_in[14];
    const float* db_b     = (const float*)d_in[15];
    const float* Alog_b   = (const float*)d_in[16];
    const float* D_b      = (const float*)d_in[17];
    const float* nrm_w    = (const float*)d_in[18];
    const float* nrm_b    = (const float*)d_in[19];
    const float* out_proj = (const float*)d_in[20];
    float* out = (float*)d_out;

    float* gh;  cudaGetSymbolAddress((void**)&gh,  g_h);
    float* guz; cudaGetSymbolAddress((void**)&guz, g_uz);
    float* got; cudaGetSymbolAddress((void**)&got, g_xc);  // g_xc[0] reused as out_proj temp

    const int conv_smem = ((POS + 3) * C_ + POS * C_ + C_ * 24 + 16 * C_ + POS * 24) * 4;
    cudaFuncSetAttribute(convproj_kernel, cudaFuncAttributeMaxDynamicSharedMemorySize, conv_smem);

    // 1. LN (tiled transpose-load)
    ln_kernel<<<BN_ * 128, 256>>>(x, ln_w, ln_b);
    // 2. in_proj GEMM: (32768 x 512)
    sgemm_tn<<<dim3(512 / 128, BL_ / 128), 256>>>(gh, in_proj, guz, BL_, 512, 256);
    // 3. conv + silu + x_proj + dt_proj (both directions, 16 pos/block)
    convproj_kernel<<<dim3(L_ / POS, BN_ * 2), 256, conv_smem>>>(
        cw_f, cb_f, xp_f, dw_f, db_f, cw_b, cb_b, xp_b, dw_b, db_b);
    // 4-6. chunked selective scan
    scan1_kernel<<<dim3(NCH, BN_ * 2), 256>>>(Alog_f, Alog_b);
    scan2_kernel<<<BN_ * 2, 256>>>();
    scan3_kernel<<<dim3(NCH, BN_ * 2), 256>>>(Alog_f, Alog_b, D_f, D_b);
    // 7. combine + silu(z) + LN
    combine_ln_kernel<<<BL_, 256>>>(nrm_w, nrm_b);
    // 8. out_proj GEMM: (32768 x 256)
    sgemm_tn<<<dim3(256 / 128, BL_ / 128), 256>>>(gh, out_proj, got, BL_, 256, 256);
    // 9. transpose + residual
    transres_kernel<<<dim3(L_ / 32, C_ / 32, BN_), 256>>>(got, x, out);
}

// round 4
// speedup vs baseline: 4.5928x; 1.2798x over previous
#include <cuda_runtime.h>
#include <cuda_bf16.h>
#include <math.h>
#include <stdint.h>

#define BN_ 8
#define C_ 256
#define L_ 4096
#define BL_ (BN_*L_)
#define NCH 64
#define CHK 64
#define POS 32

// ---------------- scratch (device globals) -----------------------------------
__device__ float  g_h  [BL_*C_];            // LN output / normalized y (reused)
__device__ float  g_uz [BL_*512];           // in_proj output: u=[:256], z=[256:]
__device__ float2 g_dtu[2][(size_t)BL_*C_]; // (dt, u) pairs, direction space
__device__ float  g_bc [2][BL_*8];          // Bc[0:4], Cc[4:8] dir space
__device__ float  g_cs [2][BN_*NCH*C_*8];   // chunk summaries: aProd[4], hEnd[4]
__device__ float  g_h0 [2][BN_*NCH*C_*4];   // corrected chunk initial states
__device__ float  g_ys [2][BL_*C_];         // scan outputs, ORIGINAL l space

// ---------------- helpers -----------------------------------------------------
__device__ __forceinline__ float siluf(float x) { return x / (1.f + __expf(-x)); }

__device__ __forceinline__ void blockReduce2(float &a, float &b, float* sA, float* sB) {
    #pragma unroll
    for (int o = 16; o; o >>= 1) {
        a += __shfl_down_sync(0xffffffffu, a, o);
        b += __shfl_down_sync(0xffffffffu, b, o);
    }
    int w = threadIdx.x >> 5, ln = threadIdx.x & 31;
    if (ln == 0) { sA[w] = a; sB[w] = b; }
    __syncthreads();
    if (threadIdx.x < 32) {
        a = (ln < 8) ? sA[ln] : 0.f;
        b = (ln < 8) ? sB[ln] : 0.f;
        #pragma unroll
        for (int o = 4; o; o >>= 1) {
            a += __shfl_down_sync(0xffffffffu, a, o);
            b += __shfl_down_sync(0xffffffffu, b, o);
        }
        if (ln == 0) { sA[0] = a; sB[0] = b; }
    }
    __syncthreads();
    a = sA[0]; b = sB[0];
    __syncthreads();
}

__device__ __forceinline__ uint32_t pkbf(__nv_bfloat16 a, __nv_bfloat16 b) {
    __nv_bfloat162 t = __halves2bfloat162(a, b);
    return *(uint32_t*)&t;
}

__device__ __forceinline__ void mma16816(float* c, const uint32_t* a, const uint32_t* b) {
    asm volatile(
        "mma.sync.aligned.m16n8k16.row.col.f32.bf16.bf16.f32 "
        "{%0,%1,%2,%3}, {%4,%5,%6,%7}, {%8,%9}, {%0,%1,%2,%3};"
        : "+f"(c[0]), "+f"(c[1]), "+f"(c[2]), "+f"(c[3])
        : "r"(a[0]), "r"(a[1]), "r"(a[2]), "r"(a[3]), "r"(b[0]), "r"(b[1]));
}

// ---------------- K1: tiled transpose + LayerNorm -----------------------------
__global__ void ln_kernel(const float* __restrict__ x,
                          const float* __restrict__ wgt,
                          const float* __restrict__ bia) {
    __shared__ float s[C_][33];
    __shared__ float smu[32], srs[32];
    int b = blockIdx.x >> 7;
    int l0 = (blockIdx.x & 127) * 32;
    int tid = threadIdx.x, w = tid >> 5, ln = tid & 31;

    for (int c = w; c < C_; c += 8)
        s[c][ln] = x[((size_t)b * C_ + c) * L_ + l0 + ln];
    __syncthreads();

    #pragma unroll
    for (int j = 0; j < 4; j++) {
        int l = w * 4 + j;
        float sm = 0.f, sq = 0.f;
        #pragma unroll
        for (int i = 0; i < 8; i++) {
            float v = s[ln + 32 * i][l];
            sm += v; sq += v * v;
        }
        #pragma unroll
        for (int o = 16; o; o >>= 1) {
            sm += __shfl_down_sync(0xffffffffu, sm, o);
            sq += __shfl_down_sync(0xffffffffu, sq, o);
        }
        if (ln == 0) {
            float mu = sm * (1.f / C_);
            float var = sq * (1.f / C_) - mu * mu;
            smu[l] = mu; srs[l] = rsqrtf(var + 1e-5f);
        }
    }
    __syncthreads();

    int c = tid;
    float wv = wgt[c], bv = bia[c];
    for (int l = 0; l < 32; l++) {
        float v = s[c][l];
        g_h[((size_t)b * L_ + l0 + l) * C_ + c] = (v - smu[l]) * srs[l] * wv + bv;
    }
}

// ---------------- K2: split-bf16 HMMA GEMM (mma.sync m16n8k16) -----------------
// C[m][n] = sum_k A[m,k]*W[n,k], K=256, tile M128 x N128, 8 warps (2m x 4n).
// mode 0: Cout[m * Nstride + n] = v
// mode 1: out_proj fused: out[(b*C + n)*L + l] = v + xres[same], l = m % 4096
#define SR 72          // smem row stride in bf16 (conflict-free fragment loads)
#define TILE_ELEM (128 * SR)
__global__ void __launch_bounds__(256, 2) gemm_hmma(
    const float* __restrict__ A, const float* __restrict__ W,
    float* __restrict__ Cout, const float* __restrict__ xres,
    int Nstride, int mode) {
    extern __shared__ __nv_bfloat16 sm[];
    __nv_bfloat16* sAh = sm;
    __nv_bfloat16* sAl = sAh + TILE_ELEM;
    __nv_bfloat16* sBh = sAl + TILE_ELEM;
    __nv_bfloat16* sBl = sBh + TILE_ELEM;

    int tid = threadIdx.x, wid = tid >> 5, lid = tid & 31;
    int g = lid >> 2, t = lid & 3;
    int warp_m = wid & 1, warp_n = wid >> 1;
    int n0 = blockIdx.x * 128, m0 = blockIdx.y * 128;

    float acc[4][4][4] = {};

    int frow = tid >> 1;                 // 0..127
    int fkh = (tid & 1) * 32;            // float offset within 64-chunk
    const float* Abase = A + (size_t)(m0 + frow) * 256 + fkh;
    const float* Wbase = W + (size_t)(n0 + frow) * 256 + fkh;

    for (int kc = 0; kc < 4; kc++) {
        __syncthreads();
        // fill A and B tiles (hi/lo split)
        #pragma unroll
        for (int half = 0; half < 2; half++) {
            const float* src = (half ? Wbase : Abase) + kc * 64;
            __nv_bfloat16* dh = (half ? sBh : sAh) + frow * SR + fkh;
            __nv_bfloat16* dl = (half ? sBl : sAl) + frow * SR + fkh;
            #pragma unroll
            for (int j = 0; j < 8; j++) {
                float4 v = *(const float4*)(src + j * 4);
                __nv_bfloat16 h0 = __float2bfloat16(v.x), h1 = __float2bfloat16(v.y);
                __nv_bfloat16 h2 = __float2bfloat16(v.z), h3 = __float2bfloat16(v.w);
                __nv_bfloat16 e0 = __float2bfloat16(v.x - __bfloat162float(h0));
                __nv_bfloat16 e1 = __float2bfloat16(v.y - __bfloat162float(h1));
                __nv_bfloat16 e2 = __float2bfloat16(v.z - __bfloat162float(h2));
                __nv_bfloat16 e3 = __float2bfloat16(v.w - __bfloat162float(h3));
                *(uint2*)(dh + j * 4) = make_uint2(pkbf(h0, h1), pkbf(h2, h3));
                *(uint2*)(dl + j * 4) = make_uint2(pkbf(e0, e1), pkbf(e2, e3));
            }
        }
        __syncthreads();

        #pragma unroll
        for (int ks = 0; ks < 4; ks++) {
            int c0 = ks * 16 + t * 2;
            // B fragments for all 4 n-frags
            uint32_t bh[4][2], bl[4][2];
            #pragma unroll
            for (int ni = 0; ni < 4; ni++) {
                int n = warp_n * 32 + ni * 8 + g;
                bh[ni][0] = *(const uint32_t*)&sBh[n * SR + c0];
                bh[ni][1] = *(const uint32_t*)&sBh[n * SR + c0 + 8];
                bl[ni][0] = *(const uint32_t*)&sBl[n * SR + c0];
                bl[ni][1] = *(const uint32_t*)&sBl[n * SR + c0 + 8];
            }
            #pragma unroll
            for (int mi = 0; mi < 4; mi++) {
                int r = warp_m * 64 + mi * 16 + g;
                uint32_t ah[4], al[4];
                ah[0] = *(const uint32_t*)&sAh[r * SR + c0];
                ah[1] = *(const uint32_t*)&sAh[(r + 8) * SR + c0];
                ah[2] = *(const uint32_t*)&sAh[r * SR + c0 + 8];
                ah[3] = *(const uint32_t*)&sAh[(r + 8) * SR + c0 + 8];
                al[0] = *(const uint32_t*)&sAl[r * SR + c0];
                al[1] = *(const uint32_t*)&sAl[(r + 8) * SR + c0];
                al[2] = *(const uint32_t*)&sAl[r * SR + c0 + 8];
                al[3] = *(const uint32_t*)&sAl[(r + 8) * SR + c0 + 8];
                #pragma unroll
                for (int ni = 0; ni < 4; ni++) {
                    mma16816(acc[mi][ni], ah, bh[ni]);
                    mma16816(acc[mi][ni], ah, bl[ni]);
                    mma16816(acc[mi][ni], al, bh[ni]);
                }
            }
        }
    }

    // epilogue
    if (mode == 0) {
        #pragma unroll
        for (int mi = 0; mi < 4; mi++) {
            int r = m0 + warp_m * 64 + mi * 16 + g;
            #pragma unroll
            for (int ni = 0; ni < 4; ni++) {
                int n = n0 + warp_n * 32 + ni * 8 + t * 2;
                *(float2*)&Cout[(size_t)r * Nstride + n] = make_float2(acc[mi][ni][0], acc[mi][ni][1]);
                *(float2*)&Cout[(size_t)(r + 8) * Nstride + n] = make_float2(acc[mi][ni][2], acc[mi][ni][3]);
            }
        }
    } else {
        int bb = m0 >> 12, l0 = m0 & 4095;
        #pragma unroll
        for (int mi = 0; mi < 4; mi++) {
            int l = l0 + warp_m * 64 + mi * 16 + g;
            #pragma unroll
            for (int ni = 0; ni < 4; ni++) {
                int ch = n0 + warp_n * 32 + ni * 8 + t * 2;
                size_t o0 = ((size_t)bb * C_ + ch) * L_ + l;
                Cout[o0]          = acc[mi][ni][0] + xres[o0];
                Cout[o0 + L_]     = acc[mi][ni][1] + xres[o0 + L_];
                Cout[o0 + 8]      = acc[mi][ni][2] + xres[o0 + 8];
                Cout[o0 + L_ + 8] = acc[mi][ni][3] + xres[o0 + L_ + 8];
            }
        }
    }
}

// ---------------- K3: conv + silu + x_proj + dt_proj (32 positions/block) ----
__global__ void convproj_kernel(
    const float* __restrict__ cw0, const float* __restrict__ cb0,
    const float* __restrict__ xp0, const float* __restrict__ dw0, const float* __restrict__ db0,
    const float* __restrict__ cw1, const float* __restrict__ cb1,
    const float* __restrict__ xp1, const float* __restrict__ dw1, const float* __restrict__ db1) {
    extern __shared__ float sh[];
    float* su   = sh;                  // 35 x 256
    float* sxc  = su + 35 * C_;        // 32 x 256
    float* sxp  = sxc + 32 * C_;       // 24 x 256 ([o][k])
    float* sdwT = sxp + 24 * C_;       // 16 x 256 ([r][c])
    float* sdbl = sdwT + 16 * C_;      // 32 x 24

    int chk = blockIdx.x;
    int b = blockIdx.y >> 1, dir = blockIdx.y & 1;
    const float* cw = dir ? cw1 : cw0;
    const float* cb = dir ? cb1 : cb0;
    const float* xp = dir ? xp1 : xp0;
    const float* dw = dir ? dw1 : dw0;
    const float* db = dir ? db1 : db0;
    int tid = threadIdx.x;
    int q0 = chk * POS;

    for (int i = tid; i < 24 * C_; i += 256) sxp[i] = xp[i];
    for (int i = tid; i < 16 * C_; i += 256) {
        int c = i >> 4, r = i & 15;
        sdwT[r * C_ + c] = dw[i];
    }
    for (int i = tid; i < 35 * C_; i += 256) {
        int j = i >> 8, c2 = i & 255;
        int q = q0 - 3 + j;
        float v = 0.f;
        if (q >= 0) {
            int phys = dir ? (L_ - 1 - q) : q;
            v = g_uz[((size_t)(b * L_ + phys)) * 512 + c2];
        }
        su[j * C_ + c2] = v;
    }
    __syncthreads();

    {   // conv + silu
        int c = tid;
        float w0 = cw[c], w1 = cw[C_ + c], w2 = cw[2 * C_ + c], w3 = cw[3 * C_ + c];
        float cbv = cb[c];
        #pragma unroll
        for (int tp = 0; tp < POS; tp++) {
            float acc = cbv;
            acc = fmaf(w0, su[(tp + 0) * C_ + c], acc);
            acc = fmaf(w1, su[(tp + 1) * C_ + c], acc);
            acc = fmaf(w2, su[(tp + 2) * C_ + c], acc);
            acc = fmaf(w3, su[(tp + 3) * C_ + c], acc);
            sxc[tp * C_ + c] = siluf(acc);
        }
    }
    __syncthreads();

    {   // x_dbl: warp w handles positions w*4 .. w*4+3
        int w = tid >> 5, ln = tid & 31;
        #pragma unroll 1
        for (int ti = 0; ti < 4; ti++) {
            int tp = w * 4 + ti;
            float xv[8];
            #pragma unroll
            for (int j = 0; j < 8; j++) xv[j] = sxc[tp * C_ + ln + 32 * j];
            #pragma unroll 1
            for (int o = 0; o < 24; o++) {
                float acc = 0.f;
                #pragma unroll
                for (int j = 0; j < 8; j++)
                    acc = fmaf(xv[j], sxp[o * C_ + ln + 32 * j], acc);
                #pragma unroll
                for (int of = 16; of; of >>= 1)
                    acc += __shfl_down_sync(0xffffffffu, acc, of);
                if (ln == 0) sdbl[tp * 24 + o] = acc;
            }
        }
    }
    __syncthreads();

    if (tid < POS * 8) {
        int pos = tid >> 3, v = tid & 7;
        g_bc[dir][(size_t)(b * L_ + q0 + pos) * 8 + v] = sdbl[pos * 24 + 16 + v];
    }

    {   // dt_proj + softplus; write (dt, u) pairs
        int c = tid;
        float dbv = db[c];
        #pragma unroll 1
        for (int pos = 0; pos < POS; pos++) {
            float val = dbv;
            #pragma unroll
            for (int r = 0; r < 16; r++)
                val = fmaf(sdbl[pos * 24 + r], sdwT[r * C_ + c], val);
            float dtv = (val > 20.f) ? val : log1pf(__expf(val));
            g_dtu[dir][(size_t)(b * L_ + q0 + pos) * C_ + c] = make_float2(dtv, sxc[pos * C_ + c]);
        }
    }
}

// ---------------- K4: scan phase 1 — chunk summaries ---------------------------
__global__ void scan1_kernel(const float* __restrict__ Alog0, const float* __restrict__ Alog1) {
    int ch = blockIdx.x;
    int b = blockIdx.y >> 1, dir = blockIdx.y & 1;
    int d = threadIdx.x;
    const float* Alog = dir ? Alog1 : Alog0;
    float Av[4];
    #pragma unroll
    for (int n = 0; n < 4; n++) Av[n] = -__expf(Alog[d * 4 + n]);

    __shared__ float sbc[CHK * 8];
    const float* gbc = g_bc[dir] + (size_t)(b * L_ + ch * CHK) * 8;
    for (int i = d; i < CHK * 8; i += 256) sbc[i] = gbc[i];
    __syncthreads();

    const float2* dtu = &g_dtu[dir][(size_t)(b * L_ + ch * CHK) * C_ + d];
    float h[4] = {0, 0, 0, 0}, aP[4] = {1, 1, 1, 1};
    #pragma unroll 4
    for (int t = 0; t < CHK; t++) {
        float2 v = dtu[(size_t)t * C_];
        float du = v.x * v.y;
        #pragma unroll
        for (int n = 0; n < 4; n++) {
            float a = __expf(v.x * Av[n]);
            h[n] = fmaf(a, h[n], du * sbc[t * 8 + n]);
            aP[n] *= a;
        }
    }
    float* cs = g_cs[dir] + ((size_t)(b * NCH + ch) * C_ + d) * 8;
    #pragma unroll
    for (int n = 0; n < 4; n++) { cs[n] = aP[n]; cs[4 + n] = h[n]; }
}

// ---------------- K5: scan phase 2 — combine chunk states ----------------------
__global__ void scan2_kernel() {
    int b = blockIdx.x >> 1, dir = blockIdx.x & 1;
    int d = threadIdx.x;
    float h[4] = {0, 0, 0, 0};
    for (int ch = 0; ch < NCH; ch++) {
        float* h0 = g_h0[dir] + ((size_t)(b * NCH + ch) * C_ + d) * 4;
        const float* cs = g_cs[dir] + ((size_t)(b * NCH + ch) * C_ + d) * 8;
        #pragma unroll
        for (int n = 0; n < 4; n++) {
            h0[n] = h[n];
            h[n] = fmaf(cs[n], h[n], cs[4 + n]);
        }
    }
}

// ---------------- K6: scan phase 3 — replay with h0, emit y (flipped) ----------
__global__ void scan3_kernel(const float* __restrict__ Alog0, const float* __restrict__ Alog1,
                             const float* __restrict__ D0, const float* __restrict__ D1) {
    int ch = blockIdx.x;
    int b = blockIdx.y >> 1, dir = blockIdx.y & 1;
    int d = threadIdx.x;
    const float* Alog = dir ? Alog1 : Alog0;
    const float* Dp   = dir ? D1 : D0;
    float Av[4];
    #pragma unroll
    for (int n = 0; n < 4; n++) Av[n] = -__expf(Alog[d * 4 + n]);
    float Dv = Dp[d];

    __shared__ float sbc[CHK * 8];
    const float* gbc = g_bc[dir] + (size_t)(b * L_ + ch * CHK) * 8;
    for (int i = d; i < CHK * 8; i += 256) sbc[i] = gbc[i];
    __syncthreads();

    const float* h0p = g_h0[dir] + ((size_t)(b * NCH + ch) * C_ + d) * 4;
    float h[4];
    #pragma unroll
    for (int n = 0; n < 4; n++) h[n] = h0p[n];

    const float2* dtu = &g_dtu[dir][(size_t)(b * L_ + ch * CHK) * C_ + d];
    #pragma unroll 4
    for (int t = 0; t < CHK; t++) {
        float2 v = dtu[(size_t)t * C_];
        float du = v.x * v.y;
        float y = v.y * Dv;
        #pragma unroll
        for (int n = 0; n < 4; n++) {
            float a = __expf(v.x * Av[n]);
            h[n] = fmaf(a, h[n], du * sbc[t * 8 + n]);
            y = fmaf(h[n], sbc[t * 8 + 4 + n], y);
        }
        int p = ch * CHK + t;
        int l = dir ? (L_ - 1 - p) : p;
        g_ys[dir][(size_t)(b * L_ + l) * C_ + d] = y;
    }
}

// ---------------- K7: combine + silu(z) + LN -> g_h ----------------------------
__global__ void combine_ln_kernel(const float* __restrict__ nw, const float* __restrict__ nb) {
    int bl = blockIdx.x;
    int c = threadIdx.x;
    float yf = g_ys[0][(size_t)bl * C_ + c];
    float yb = g_ys[1][(size_t)bl * C_ + c];
    float z  = g_uz[(size_t)bl * 512 + 256 + c];
    float yv = 0.5f * (yf + yb) * siluf(z);

    float a = yv, q = yv * yv;
    __shared__ float sA[8], sB[8];
    blockReduce2(a, q, sA, sB);
    float mu  = a * (1.f / C_);
    float var = q * (1.f / C_) - mu * mu;
    g_h[(size_t)bl * C_ + c] = (yv - mu) * rsqrtf(var + 1e-5f) * nw[c] + nb[c];
}

// ---------------- launch ---------------------------------------------------------
extern "C" void kernel_launch(void* const* d_in, const int* in_sizes, int n_in,
                              void* d_out, int out_size) {
    const float* x        = (const float*)d_in[0];
    const float* ln_w     = (const float*)d_in[1];
    const float* ln_b     = (const float*)d_in[2];
    const float* in_proj  = (const float*)d_in[3];
    const float* cw_f     = (const float*)d_in[4];
    const float* cb_f     = (const float*)d_in[5];
    const float* xp_f     = (const float*)d_in[6];
    const float* dw_f     = (const float*)d_in[7];
    const float* db_f     = (const float*)d_in[8];
    const float* Alog_f   = (const float*)d_in[9];
    const float* D_f      = (const float*)d_in[10];
    const float* cw_b     = (const float*)d_in[11];
    const float* cb_b     = (const float*)d_in[12];
    const float* xp_b     = (const float*)d_in[13];
    const float* dw_b     = (const float*)d_in[14];
    const float* db_b     = (const float*)d_in[15];
    const float* Alog_b   = (const float*)d_in[16];
    const float* D_b      = (const float*)d_in[17];
    const float* nrm_w    = (const float*)d_in[18];
    const float* nrm_b    = (const float*)d_in[19];
    const float* out_proj = (const float*)d_in[20];
    float* out = (float*)d_out;

    float* gh;  cudaGetSymbolAddress((void**)&gh,  g_h);
    float* guz; cudaGetSymbolAddress((void**)&guz, g_uz);

    const int gemm_smem = 4 * TILE_ELEM * 2;   // 73728 B
    cudaFuncSetAttribute(gemm_hmma, cudaFuncAttributeMaxDynamicSharedMemorySize, gemm_smem);
    const int conv_smem = (35 * C_ + 32 * C_ + 24 * C_ + 16 * C_ + 32 * 24) * 4;
    cudaFuncSetAttribute(convproj_kernel, cudaFuncAttributeMaxDynamicSharedMemorySize, conv_smem);

    // 1. LN (tiled transpose-load)
    ln_kernel<<<BN_ * 128, 256>>>(x, ln_w, ln_b);
    // 2. in_proj GEMM: (32768 x 512) split-bf16 HMMA
    gemm_hmma<<<dim3(4, BL_ / 128), 256, gemm_smem>>>(gh, in_proj, guz, nullptr, 512, 0);
    // 3. conv + silu + x_proj + dt_proj (both directions)
    convproj_kernel<<<dim3(L_ / POS, BN_ * 2), 256, conv_smem>>>(
        cw_f, cb_f, xp_f, dw_f, db_f, cw_b, cb_b, xp_b, dw_b, db_b);
    // 4-6. chunked selective scan
    scan1_kernel<<<dim3(NCH, BN_ * 2), 256>>>(Alog_f, Alog_b);
    scan2_kernel<<<BN_ * 2, 256>>>();
    scan3_kernel<<<dim3(NCH, BN_ * 2), 256>>>(Alog_f, Alog_b, D_f, D_b);
    // 7. combine + silu(z) + LN
    combine_ln_kernel<<<BL_, 256>>>(nrm_w, nrm_b);
    // 8. out_proj GEMM + residual + transposed write (fused epilogue)
    gemm_hmma<<<dim3(2, BL_ / 128), 256, gemm_smem>>>(gh, out_proj, out, x, 256, 1);
}

// round 5
// speedup vs baseline: 4.6676x; 1.0163x over previous
#include <cuda_runtime.h>
#include <cuda_bf16.h>
#include <math.h>
#include <stdint.h>

#define BN_ 8
#define C_ 256
#define L_ 4096
#define BL_ (BN_*L_)
#define NCH 128
#define CHK 32
#define POS 32

// ---------------- scratch (device globals) -----------------------------------
__device__ float  g_h  [BL_*C_];            // LN output / normalized y (reused)
__device__ float  g_uz [BL_*512];           // in_proj output: u=[:256], z=[256:]
__device__ float2 g_dtu[2][(size_t)BL_*C_]; // (dt, u) pairs, direction space
__device__ float  g_bc [2][BL_*8];          // Bc[0:4], Cc[4:8] dir space
__device__ float  g_cs [2][BN_*NCH*C_*8];   // chunk summaries: aProd[4], hEnd[4]
__device__ float  g_h0 [2][BN_*NCH*C_*4];   // corrected chunk initial states

// ---------------- helpers -----------------------------------------------------
__device__ __forceinline__ float siluf(float x) { return x / (1.f + __expf(-x)); }

__device__ __forceinline__ uint32_t pkbf(__nv_bfloat16 a, __nv_bfloat16 b) {
    __nv_bfloat162 t = __halves2bfloat162(a, b);
    return *(uint32_t*)&t;
}

__device__ __forceinline__ void mma16816(float* c, const uint32_t* a, const uint32_t* b) {
    asm volatile(
        "mma.sync.aligned.m16n8k16.row.col.f32.bf16.bf16.f32 "
        "{%0,%1,%2,%3}, {%4,%5,%6,%7}, {%8,%9}, {%0,%1,%2,%3};"
        : "+f"(c[0]), "+f"(c[1]), "+f"(c[2]), "+f"(c[3])
        : "r"(a[0]), "r"(a[1]), "r"(a[2]), "r"(a[3]), "r"(b[0]), "r"(b[1]));
}

// ---------------- K1: tiled transpose + LayerNorm -----------------------------
__global__ void ln_kernel(const float* __restrict__ x,
                          const float* __restrict__ wgt,
                          const float* __restrict__ bia) {
    __shared__ float s[C_][33];
    __shared__ float smu[32], srs[32];
    int b = blockIdx.x >> 7;
    int l0 = (blockIdx.x & 127) * 32;
    int tid = threadIdx.x, w = tid >> 5, ln = tid & 31;

    for (int c = w; c < C_; c += 8)
        s[c][ln] = x[((size_t)b * C_ + c) * L_ + l0 + ln];
    __syncthreads();

    #pragma unroll
    for (int j = 0; j < 4; j++) {
        int l = w * 4 + j;
        float sm = 0.f, sq = 0.f;
        #pragma unroll
        for (int i = 0; i < 8; i++) {
            float v = s[ln + 32 * i][l];
            sm += v; sq += v * v;
        }
        #pragma unroll
        for (int o = 16; o; o >>= 1) {
            sm += __shfl_down_sync(0xffffffffu, sm, o);
            sq += __shfl_down_sync(0xffffffffu, sq, o);
        }
        if (ln == 0) {
            float mu = sm * (1.f / C_);
            float var = sq * (1.f / C_) - mu * mu;
            smu[l] = mu; srs[l] = rsqrtf(var + 1e-5f);
        }
    }
    __syncthreads();

    int c = tid;
    float wv = wgt[c], bv = bia[c];
    for (int l = 0; l < 32; l++) {
        float v = s[c][l];
        g_h[((size_t)b * L_ + l0 + l) * C_ + c] = (v - smu[l]) * srs[l] * wv + bv;
    }
}

// ---------------- K2: split-bf16 HMMA GEMM (mma.sync m16n8k16) -----------------
#define SR 72
#define TILE_ELEM (128 * SR)
__global__ void __launch_bounds__(256, 2) gemm_hmma(
    const float* __restrict__ A, const float* __restrict__ W,
    float* __restrict__ Cout, const float* __restrict__ xres,
    int Nstride, int mode) {
    extern __shared__ __nv_bfloat16 sm[];
    __nv_bfloat16* sAh = sm;
    __nv_bfloat16* sAl = sAh + TILE_ELEM;
    __nv_bfloat16* sBh = sAl + TILE_ELEM;
    __nv_bfloat16* sBl = sBh + TILE_ELEM;

    int tid = threadIdx.x, wid = tid >> 5, lid = tid & 31;
    int g = lid >> 2, t = lid & 3;
    int warp_m = wid & 1, warp_n = wid >> 1;
    int n0 = blockIdx.x * 128, m0 = blockIdx.y * 128;

    float acc[4][4][4] = {};

    int frow = tid >> 1;
    int fkh = (tid & 1) * 32;
    const float* Abase = A + (size_t)(m0 + frow) * 256 + fkh;
    const float* Wbase = W + (size_t)(n0 + frow) * 256 + fkh;

    for (int kc = 0; kc < 4; kc++) {
        __syncthreads();
        #pragma unroll
        for (int half = 0; half < 2; half++) {
            const float* src = (half ? Wbase : Abase) + kc * 64;
            __nv_bfloat16* dh = (half ? sBh : sAh) + frow * SR + fkh;
            __nv_bfloat16* dl = (half ? sBl : sAl) + frow * SR + fkh;
            #pragma unroll
            for (int j = 0; j < 8; j++) {
                float4 v = *(const float4*)(src + j * 4);
                __nv_bfloat16 h0 = __float2bfloat16(v.x), h1 = __float2bfloat16(v.y);
                __nv_bfloat16 h2 = __float2bfloat16(v.z), h3 = __float2bfloat16(v.w);
                __nv_bfloat16 e0 = __float2bfloat16(v.x - __bfloat162float(h0));
                __nv_bfloat16 e1 = __float2bfloat16(v.y - __bfloat162float(h1));
                __nv_bfloat16 e2 = __float2bfloat16(v.z - __bfloat162float(h2));
                __nv_bfloat16 e3 = __float2bfloat16(v.w - __bfloat162float(h3));
                *(uint2*)(dh + j * 4) = make_uint2(pkbf(h0, h1), pkbf(h2, h3));
                *(uint2*)(dl + j * 4) = make_uint2(pkbf(e0, e1), pkbf(e2, e3));
            }
        }
        __syncthreads();

        #pragma unroll
        for (int ks = 0; ks < 4; ks++) {
            int c0 = ks * 16 + t * 2;
            uint32_t bh[4][2], bl[4][2];
            #pragma unroll
            for (int ni = 0; ni < 4; ni++) {
                int n = warp_n * 32 + ni * 8 + g;
                bh[ni][0] = *(const uint32_t*)&sBh[n * SR + c0];
                bh[ni][1] = *(const uint32_t*)&sBh[n * SR + c0 + 8];
                bl[ni][0] = *(const uint32_t*)&sBl[n * SR + c0];
                bl[ni][1] = *(const uint32_t*)&sBl[n * SR + c0 + 8];
            }
            #pragma unroll
            for (int mi = 0; mi < 4; mi++) {
                int r = warp_m * 64 + mi * 16 + g;
                uint32_t ah[4], al[4];
                ah[0] = *(const uint32_t*)&sAh[r * SR + c0];
                ah[1] = *(const uint32_t*)&sAh[(r + 8) * SR + c0];
                ah[2] = *(const uint32_t*)&sAh[r * SR + c0 + 8];
                ah[3] = *(const uint32_t*)&sAh[(r + 8) * SR + c0 + 8];
                al[0] = *(const uint32_t*)&sAl[r * SR + c0];
                al[1] = *(const uint32_t*)&sAl[(r + 8) * SR + c0];
                al[2] = *(const uint32_t*)&sAl[r * SR + c0 + 8];
                al[3] = *(const uint32_t*)&sAl[(r + 8) * SR + c0 + 8];
                #pragma unroll
                for (int ni = 0; ni < 4; ni++) {
                    mma16816(acc[mi][ni], ah, bh[ni]);
                    mma16816(acc[mi][ni], ah, bl[ni]);
                    mma16816(acc[mi][ni], al, bh[ni]);
                }
            }
        }
    }

    if (mode == 0) {
        #pragma unroll
        for (int mi = 0; mi < 4; mi++) {
            int r = m0 + warp_m * 64 + mi * 16 + g;
            #pragma unroll
            for (int ni = 0; ni < 4; ni++) {
                int n = n0 + warp_n * 32 + ni * 8 + t * 2;
                *(float2*)&Cout[(size_t)r * Nstride + n] = make_float2(acc[mi][ni][0], acc[mi][ni][1]);
                *(float2*)&Cout[(size_t)(r + 8) * Nstride + n] = make_float2(acc[mi][ni][2], acc[mi][ni][3]);
            }
        }
    } else {
        int bb = m0 >> 12, l0 = m0 & 4095;
        #pragma unroll
        for (int mi = 0; mi < 4; mi++) {
            int l = l0 + warp_m * 64 + mi * 16 + g;
            #pragma unroll
            for (int ni = 0; ni < 4; ni++) {
                int ch = n0 + warp_n * 32 + ni * 8 + t * 2;
                size_t o0 = ((size_t)bb * C_ + ch) * L_ + l;
                Cout[o0]          = acc[mi][ni][0] + xres[o0];
                Cout[o0 + L_]     = acc[mi][ni][1] + xres[o0 + L_];
                Cout[o0 + 8]      = acc[mi][ni][2] + xres[o0 + 8];
                Cout[o0 + L_ + 8] = acc[mi][ni][3] + xres[o0 + L_ + 8];
            }
        }
    }
}

// ---------------- K3: conv + silu + x_proj + dt_proj + scan-phase1 ------------
__global__ void convscan_kernel(
    const float* __restrict__ cw0, const float* __restrict__ cb0,
    const float* __restrict__ xp0, const float* __restrict__ dw0, const float* __restrict__ db0,
    const float* __restrict__ Alog0,
    const float* __restrict__ cw1, const float* __restrict__ cb1,
    const float* __restrict__ xp1, const float* __restrict__ dw1, const float* __restrict__ db1,
    const float* __restrict__ Alog1) {
    extern __shared__ float sh[];
    float* su   = sh;                  // 35 x 256
    float* sxc  = su + 35 * C_;        // 32 x 256
    float* sxp  = sxc + 32 * C_;       // 24 x 256 ([o][k])
    float* sdwT = sxp + 24 * C_;       // 16 x 256 ([r][c])
    float* sdbl = sdwT + 16 * C_;      // 32 x 24

    int chk = blockIdx.x;
    int b = blockIdx.y >> 1, dir = blockIdx.y & 1;
    const float* cw = dir ? cw1 : cw0;
    const float* cb = dir ? cb1 : cb0;
    const float* xp = dir ? xp1 : xp0;
    const float* dw = dir ? dw1 : dw0;
    const float* db = dir ? db1 : db0;
    const float* Alog = dir ? Alog1 : Alog0;
    int tid = threadIdx.x;
    int q0 = chk * POS;

    for (int i = tid; i < 24 * C_; i += 256) sxp[i] = xp[i];
    for (int i = tid; i < 16 * C_; i += 256) {
        int c = i >> 4, r = i & 15;
        sdwT[r * C_ + c] = dw[i];
    }
    for (int i = tid; i < 35 * C_; i += 256) {
        int j = i >> 8, c2 = i & 255;
        int q = q0 - 3 + j;
        float v = 0.f;
        if (q >= 0) {
            int phys = dir ? (L_ - 1 - q) : q;
            v = g_uz[((size_t)(b * L_ + phys)) * 512 + c2];
        }
        su[j * C_ + c2] = v;
    }
    __syncthreads();

    {   // conv + silu
        int c = tid;
        float w0 = cw[c], w1 = cw[C_ + c], w2 = cw[2 * C_ + c], w3 = cw[3 * C_ + c];
        float cbv = cb[c];
        #pragma unroll
        for (int tp = 0; tp < POS; tp++) {
            float acc = cbv;
            acc = fmaf(w0, su[(tp + 0) * C_ + c], acc);
            acc = fmaf(w1, su[(tp + 1) * C_ + c], acc);
            acc = fmaf(w2, su[(tp + 2) * C_ + c], acc);
            acc = fmaf(w3, su[(tp + 3) * C_ + c], acc);
            sxc[tp * C_ + c] = siluf(acc);
        }
    }
    __syncthreads();

    {   // x_dbl: warp w handles positions w*4 .. w*4+3
        int w = tid >> 5, ln = tid & 31;
        #pragma unroll 1
        for (int ti = 0; ti < 4; ti++) {
            int tp = w * 4 + ti;
            float xv[8];
            #pragma unroll
            for (int j = 0; j < 8; j++) xv[j] = sxc[tp * C_ + ln + 32 * j];
            #pragma unroll 1
            for (int o = 0; o < 24; o++) {
                float acc = 0.f;
                #pragma unroll
                for (int j = 0; j < 8; j++)
                    acc = fmaf(xv[j], sxp[o * C_ + ln + 32 * j], acc);
                #pragma unroll
                for (int of = 16; of; of >>= 1)
                    acc += __shfl_down_sync(0xffffffffu, acc, of);
                if (ln == 0) sdbl[tp * 24 + o] = acc;
            }
        }
    }
    __syncthreads();

    if (tid < POS * 8) {
        int pos = tid >> 3, v = tid & 7;
        g_bc[dir][(size_t)(b * L_ + q0 + pos) * 8 + v] = sdbl[pos * 24 + 16 + v];
    }

    {   // dt_proj + softplus + chunk-local scan summary
        int c = tid;
        float dbv = db[c];
        float Av[4];
        #pragma unroll
        for (int n = 0; n < 4; n++) Av[n] = -__expf(Alog[c * 4 + n]);
        float h[4] = {0, 0, 0, 0}, aP[4] = {1, 1, 1, 1};
        #pragma unroll 1
        for (int pos = 0; pos < POS; pos++) {
            float val = dbv;
            #pragma unroll
            for (int r = 0; r < 16; r++)
                val = fmaf(sdbl[pos * 24 + r], sdwT[r * C_ + c], val);
            float dtv = (val > 20.f) ? val : log1pf(__expf(val));
            float uu = sxc[pos * C_ + c];
            g_dtu[dir][(size_t)(b * L_ + q0 + pos) * C_ + c] = make_float2(dtv, uu);
            float du = dtv * uu;
            #pragma unroll
            for (int n = 0; n < 4; n++) {
                float a = __expf(dtv * Av[n]);
                h[n] = fmaf(a, h[n], du * sdbl[pos * 24 + 16 + n]);
                aP[n] *= a;
            }
        }
        float* cs = g_cs[dir] + ((size_t)(b * NCH + chk) * C_ + c) * 8;
        #pragma unroll
        for (int n = 0; n < 4; n++) { cs[n] = aP[n]; cs[4 + n] = h[n]; }
    }
}

// ---------------- K4: scan phase 2 — combine chunk states ----------------------
__global__ void scan2_kernel() {
    int b = blockIdx.x >> 1, dir = blockIdx.x & 1;
    int d = threadIdx.x;
    float h[4] = {0, 0, 0, 0};
    #pragma unroll 4
    for (int ch = 0; ch < NCH; ch++) {
        float* h0 = g_h0[dir] + ((size_t)(b * NCH + ch) * C_ + d) * 4;
        const float* cs = g_cs[dir] + ((size_t)(b * NCH + ch) * C_ + d) * 8;
        #pragma unroll
        for (int n = 0; n < 4; n++) {
            h0[n] = h[n];
            h[n] = fmaf(cs[n], h[n], cs[4 + n]);
        }
    }
}

// ---------------- K5: fused replay(f+b) + combine + silu(z) + LN ---------------
__global__ void scan3_fused_kernel(
    const float* __restrict__ Alog0, const float* __restrict__ Alog1,
    const float* __restrict__ D0, const float* __restrict__ D1,
    const float* __restrict__ nw, const float* __restrict__ nb) {
    __shared__ float sbcf[CHK * 8], sbcb[CHK * 8];
    __shared__ float ysm[CHK * C_];
    __shared__ float smu[CHK], srs[CHK];

    int ch = blockIdx.x;
    int b  = blockIdx.y;
    int c  = threadIdx.x;
    int chb = NCH - 1 - ch;
    int l0 = ch * CHK;

    {
        const float* gf = g_bc[0] + (size_t)(b * L_ + ch * CHK) * 8;
        const float* gb = g_bc[1] + (size_t)(b * L_ + chb * CHK) * 8;
        if (c < CHK * 8) { sbcf[c] = gf[c]; sbcb[c] = gb[c]; }
    }
    __syncthreads();

    // forward replay: writes ysm
    {
        float Av[4];
        #pragma unroll
        for (int n = 0; n < 4; n++) Av[n] = -__expf(Alog0[c * 4 + n]);
        float Dv = D0[c];
        const float* h0p = g_h0[0] + ((size_t)(b * NCH + ch) * C_ + c) * 4;
        float h[4];
        #pragma unroll
        for (int n = 0; n < 4; n++) h[n] = h0p[n];
        const float2* dtu = &g_dtu[0][(size_t)(b * L_ + l0) * C_ + c];
        #pragma unroll 4
        for (int t = 0; t < CHK; t++) {
            float2 v = dtu[(size_t)t * C_];
            float du = v.x * v.y;
            float y = v.y * Dv;
            #pragma unroll
            for (int n = 0; n < 4; n++) {
                float a = __expf(v.x * Av[n]);
                h[n] = fmaf(a, h[n], du * sbcf[t * 8 + n]);
                y = fmaf(h[n], sbcf[t * 8 + 4 + n], y);
            }
            ysm[t * C_ + c] = y;
        }
    }
    // backward replay: accumulates into ysm (same thread owns column c — no race)
    {
        float Av[4];
        #pragma unroll
        for (int n = 0; n < 4; n++) Av[n] = -__expf(Alog1[c * 4 + n]);
        float Dv = D1[c];
        const float* h0p = g_h0[1] + ((size_t)(b * NCH + chb) * C_ + c) * 4;
        float h[4];
        #pragma unroll
        for (int n = 0; n < 4; n++) h[n] = h0p[n];
        const float2* dtu = &g_dtu[1][(size_t)(b * L_ + chb * CHK) * C_ + c];
        #pragma unroll 4
        for (int tb = 0; tb < CHK; tb++) {
            float2 v = dtu[(size_t)tb * C_];
            float du = v.x * v.y;
            float y = v.y * Dv;
            #pragma unroll
            for (int n = 0; n < 4; n++) {
                float a = __expf(v.x * Av[n]);
                h[n] = fmaf(a, h[n], du * sbcb[tb * 8 + n]);
                y = fmaf(h[n], sbcb[tb * 8 + 4 + n], y);
            }
            ysm[(CHK - 1 - tb) * C_ + c] += y;
        }
    }
    // z-gate
    {
        const float* zp = &g_uz[(size_t)(b * L_ + l0) * 512 + 256 + c];
        #pragma unroll 4
        for (int t = 0; t < CHK; t++) {
            float z = zp[(size_t)t * 512];
            ysm[t * C_ + c] = 0.5f * ysm[t * C_ + c] * siluf(z);
        }
    }
    __syncthreads();
    // LN stats: warp w handles positions w*4 .. w*4+3
    {
        int w = c >> 5, ln = c & 31;
        #pragma unroll
        for (int j = 0; j < 4; j++) {
            int t = w * 4 + j;
            float sm = 0.f, sq = 0.f;
            #pragma unroll
            for (int i = 0; i < 8; i++) {
                float v = ysm[t * C_ + ln + 32 * i];
                sm += v; sq += v * v;
            }
            #pragma unroll
            for (int o = 16; o; o >>= 1) {
                sm += __shfl_down_sync(0xffffffffu, sm, o);
                sq += __shfl_down_sync(0xffffffffu, sq, o);
            }
            if (ln == 0) {
                float mu = sm * (1.f / C_);
                float var = sq * (1.f / C_) - mu * mu;
                smu[t] = mu; srs[t] = rsqrtf(var + 1e-5f);
            }
        }
    }
    __syncthreads();
    {
        float wv = nw[c], bv = nb[c];
        #pragma unroll 4
        for (int t = 0; t < CHK; t++) {
            float v = ysm[t * C_ + c];
            g_h[(size_t)(b * L_ + l0 + t) * C_ + c] = (v - smu[t]) * srs[t] * wv + bv;
        }
    }
}

// ---------------- launch ---------------------------------------------------------
extern "C" void kernel_launch(void* const* d_in, const int* in_sizes, int n_in,
                              void* d_out, int out_size) {
    const float* x        = (const float*)d_in[0];
    const float* ln_w     = (const float*)d_in[1];
    const float* ln_b     = (const float*)d_in[2];
    const float* in_proj  = (const float*)d_in[3];
    const float* cw_f     = (const float*)d_in[4];
    const float* cb_f     = (const float*)d_in[5];
    const float* xp_f     = (const float*)d_in[6];
    const float* dw_f     = (const float*)d_in[7];
    const float* db_f     = (const float*)d_in[8];
    const float* Alog_f   = (const float*)d_in[9];
    const float* D_f      = (const float*)d_in[10];
    const float* cw_b     = (const float*)d_in[11];
    const float* cb_b     = (const float*)d_in[12];
    const float* xp_b     = (const float*)d_in[13];
    const float* dw_b     = (const float*)d_in[14];
    const float* db_b     = (const float*)d_in[15];
    const float* Alog_b   = (const float*)d_in[16];
    const float* D_b      = (const float*)d_in[17];
    const float* nrm_w    = (const float*)d_in[18];
    const float* nrm_b    = (const float*)d_in[19];
    const float* out_proj = (const float*)d_in[20];
    float* out = (float*)d_out;

    float* gh;  cudaGetSymbolAddress((void**)&gh,  g_h);
    float* guz; cudaGetSymbolAddress((void**)&guz, g_uz);

    const int gemm_smem = 4 * TILE_ELEM * 2;   // 73728 B
    cudaFuncSetAttribute(gemm_hmma, cudaFuncAttributeMaxDynamicSharedMemorySize, gemm_smem);
    const int conv_smem = (35 * C_ + 32 * C_ + 24 * C_ + 16 * C_ + 32 * 24) * 4;
    cudaFuncSetAttribute(convscan_kernel, cudaFuncAttributeMaxDynamicSharedMemorySize, conv_smem);

    // 1. LN (tiled transpose-load)
    ln_kernel<<<BN_ * 128, 256>>>(x, ln_w, ln_b);
    // 2. in_proj GEMM (32768 x 512) split-bf16 HMMA
    gemm_hmma<<<dim3(4, BL_ / 128), 256, gemm_smem>>>(gh, in_proj, guz, nullptr, 512, 0);
    // 3. conv + silu + x_proj + dt_proj + scan-phase1 (both directions)
    convscan_kernel<<<dim3(NCH, BN_ * 2), 256, conv_smem>>>(
        cw_f, cb_f, xp_f, dw_f, db_f, Alog_f,
        cw_b, cb_b, xp_b, dw_b, db_b, Alog_b);
    // 4. scan phase 2
    scan2_kernel<<<BN_ * 2, 256>>>();
    // 5. fused replay + combine + silu(z) + LN
    scan3_fused_kernel<<<dim3(NCH, BN_), 256>>>(Alog_f, Alog_b, D_f, D_b, nrm_w, nrm_b);
    // 6. out_proj GEMM + residual + transposed write (fused epilogue)
    gemm_hmma<<<dim3(2, BL_ / 128), 256, gemm_smem>>>(gh, out_proj, out, x, 256, 1);
}

// round 6
// speedup vs baseline: 4.7410x; 1.0157x over previous
#include <cuda_runtime.h>
#include <cuda_bf16.h>
#include <math.h>
#include <stdint.h>

#define BN_ 8
#define C_ 256
#define L_ 4096
#define BL_ (BN_*L_)
#define NCH 128
#define CHK 32
#define POS 32

// ---------------- scratch (device globals) -----------------------------------
__device__ float  g_h  [BL_*C_];            // LN output / normalized y (reused)
__device__ float  g_uz [BL_*512];           // in_proj output: u=[:256], z=[256:]
__device__ float2 g_dtu[2][(size_t)BL_*C_]; // (dt, u) pairs, direction space
__device__ float  g_bc [2][BL_*8];          // Bc[0:4], Cc[4:8] dir space
__device__ float  g_cs [2][BN_*NCH*C_*8];   // chunk summaries: aProd[4], hEnd[4]
__device__ float  g_h0 [2][BN_*NCH*C_*4];   // corrected chunk initial states

// ---------------- helpers -----------------------------------------------------
__device__ __forceinline__ float siluf(float x) { return x / (1.f + __expf(-x)); }

__device__ __forceinline__ uint32_t pkbf(__nv_bfloat16 a, __nv_bfloat16 b) {
    __nv_bfloat162 t = __halves2bfloat162(a, b);
    return *(uint32_t*)&t;
}

__device__ __forceinline__ void mma16816(float* c, const uint32_t* a, const uint32_t* b) {
    asm volatile(
        "mma.sync.aligned.m16n8k16.row.col.f32.bf16.bf16.f32 "
        "{%0,%1,%2,%3}, {%4,%5,%6,%7}, {%8,%9}, {%0,%1,%2,%3};"
        : "+f"(c[0]), "+f"(c[1]), "+f"(c[2]), "+f"(c[3])
        : "r"(a[0]), "r"(a[1]), "r"(a[2]), "r"(a[3]), "r"(b[0]), "r"(b[1]));
}

// ---------------- K1: tiled transpose + LayerNorm -----------------------------
__global__ void ln_kernel(const float* __restrict__ x,
                          const float* __restrict__ wgt,
                          const float* __restrict__ bia) {
    __shared__ float s[C_][33];
    __shared__ float smu[32], srs[32];
    int b = blockIdx.x >> 7;
    int l0 = (blockIdx.x & 127) * 32;
    int tid = threadIdx.x, w = tid >> 5, ln = tid & 31;

    for (int c = w; c < C_; c += 8)
        s[c][ln] = x[((size_t)b * C_ + c) * L_ + l0 + ln];
    __syncthreads();

    #pragma unroll
    for (int j = 0; j < 4; j++) {
        int l = w * 4 + j;
        float sm = 0.f, sq = 0.f;
        #pragma unroll
        for (int i = 0; i < 8; i++) {
            float v = s[ln + 32 * i][l];
            sm += v; sq += v * v;
        }
        #pragma unroll
        for (int o = 16; o; o >>= 1) {
            sm += __shfl_down_sync(0xffffffffu, sm, o);
            sq += __shfl_down_sync(0xffffffffu, sq, o);
        }
        if (ln == 0) {
            float mu = sm * (1.f / C_);
            float var = sq * (1.f / C_) - mu * mu;
            smu[l] = mu; srs[l] = rsqrtf(var + 1e-5f);
        }
    }
    __syncthreads();

    int c = tid;
    float wv = wgt[c], bv = bia[c];
    for (int l = 0; l < 32; l++) {
        float v = s[c][l];
        g_h[((size_t)b * L_ + l0 + l) * C_ + c] = (v - smu[l]) * srs[l] * wv + bv;
    }
}

// ---------------- K2: split-bf16 HMMA GEMM (mma.sync m16n8k16) -----------------
#define SR 72
#define TILE_ELEM (128 * SR)
__global__ void __launch_bounds__(256, 2) gemm_hmma(
    const float* __restrict__ A, const float* __restrict__ W,
    float* __restrict__ Cout, const float* __restrict__ xres,
    int Nstride, int mode) {
    extern __shared__ __nv_bfloat16 sm[];
    __nv_bfloat16* sAh = sm;
    __nv_bfloat16* sAl = sAh + TILE_ELEM;
    __nv_bfloat16* sBh = sAl + TILE_ELEM;
    __nv_bfloat16* sBl = sBh + TILE_ELEM;

    int tid = threadIdx.x, wid = tid >> 5, lid = tid & 31;
    int g = lid >> 2, t = lid & 3;
    int warp_m = wid & 1, warp_n = wid >> 1;
    int n0 = blockIdx.x * 128, m0 = blockIdx.y * 128;

    float acc[4][4][4] = {};

    int frow = tid >> 1;
    int fkh = (tid & 1) * 32;
    const float* Abase = A + (size_t)(m0 + frow) * 256 + fkh;
    const float* Wbase = W + (size_t)(n0 + frow) * 256 + fkh;

    for (int kc = 0; kc < 4; kc++) {
        __syncthreads();
        #pragma unroll
        for (int half = 0; half < 2; half++) {
            const float* src = (half ? Wbase : Abase) + kc * 64;
            __nv_bfloat16* dh = (half ? sBh : sAh) + frow * SR + fkh;
            __nv_bfloat16* dl = (half ? sBl : sAl) + frow * SR + fkh;
            #pragma unroll
            for (int j = 0; j < 8; j++) {
                float4 v = *(const float4*)(src + j * 4);
                __nv_bfloat16 h0 = __float2bfloat16(v.x), h1 = __float2bfloat16(v.y);
                __nv_bfloat16 h2 = __float2bfloat16(v.z), h3 = __float2bfloat16(v.w);
                __nv_bfloat16 e0 = __float2bfloat16(v.x - __bfloat162float(h0));
                __nv_bfloat16 e1 = __float2bfloat16(v.y - __bfloat162float(h1));
                __nv_bfloat16 e2 = __float2bfloat16(v.z - __bfloat162float(h2));
                __nv_bfloat16 e3 = __float2bfloat16(v.w - __bfloat162float(h3));
                *(uint2*)(dh + j * 4) = make_uint2(pkbf(h0, h1), pkbf(h2, h3));
                *(uint2*)(dl + j * 4) = make_uint2(pkbf(e0, e1), pkbf(e2, e3));
            }
        }
        __syncthreads();

        #pragma unroll
        for (int ks = 0; ks < 4; ks++) {
            int c0 = ks * 16 + t * 2;
            uint32_t bh[4][2], bl[4][2];
            #pragma unroll
            for (int ni = 0; ni < 4; ni++) {
                int n = warp_n * 32 + ni * 8 + g;
                bh[ni][0] = *(const uint32_t*)&sBh[n * SR + c0];
                bh[ni][1] = *(const uint32_t*)&sBh[n * SR + c0 + 8];
                bl[ni][0] = *(const uint32_t*)&sBl[n * SR + c0];
                bl[ni][1] = *(const uint32_t*)&sBl[n * SR + c0 + 8];
            }
            #pragma unroll
            for (int mi = 0; mi < 4; mi++) {
                int r = warp_m * 64 + mi * 16 + g;
                uint32_t ah[4], al[4];
                ah[0] = *(const uint32_t*)&sAh[r * SR + c0];
                ah[1] = *(const uint32_t*)&sAh[(r + 8) * SR + c0];
                ah[2] = *(const uint32_t*)&sAh[r * SR + c0 + 8];
                ah[3] = *(const uint32_t*)&sAh[(r + 8) * SR + c0 + 8];
                al[0] = *(const uint32_t*)&sAl[r * SR + c0];
                al[1] = *(const uint32_t*)&sAl[(r + 8) * SR + c0];
                al[2] = *(const uint32_t*)&sAl[r * SR + c0 + 8];
                al[3] = *(const uint32_t*)&sAl[(r + 8) * SR + c0 + 8];
                #pragma unroll
                for (int ni = 0; ni < 4; ni++) {
                    mma16816(acc[mi][ni], ah, bh[ni]);
                    mma16816(acc[mi][ni], ah, bl[ni]);
                    mma16816(acc[mi][ni], al, bh[ni]);
                }
            }
        }
    }

    if (mode == 0) {
        #pragma unroll
        for (int mi = 0; mi < 4; mi++) {
            int r = m0 + warp_m * 64 + mi * 16 + g;
            #pragma unroll
            for (int ni = 0; ni < 4; ni++) {
                int n = n0 + warp_n * 32 + ni * 8 + t * 2;
                *(float2*)&Cout[(size_t)r * Nstride + n] = make_float2(acc[mi][ni][0], acc[mi][ni][1]);
                *(float2*)&Cout[(size_t)(r + 8) * Nstride + n] = make_float2(acc[mi][ni][2], acc[mi][ni][3]);
            }
        }
    } else {
        int bb = m0 >> 12, l0 = m0 & 4095;
        #pragma unroll
        for (int mi = 0; mi < 4; mi++) {
            int l = l0 + warp_m * 64 + mi * 16 + g;
            #pragma unroll
            for (int ni = 0; ni < 4; ni++) {
                int ch = n0 + warp_n * 32 + ni * 8 + t * 2;
                size_t o0 = ((size_t)bb * C_ + ch) * L_ + l;
                Cout[o0]          = acc[mi][ni][0] + xres[o0];
                Cout[o0 + L_]     = acc[mi][ni][1] + xres[o0 + L_];
                Cout[o0 + 8]      = acc[mi][ni][2] + xres[o0 + 8];
                Cout[o0 + L_ + 8] = acc[mi][ni][3] + xres[o0 + L_ + 8];
            }
        }
    }
}

// ---------------- K3: conv + silu + x_proj + dt_proj + scan-phase1 ------------
__global__ void convscan_kernel(
    const float* __restrict__ cw0, const float* __restrict__ cb0,
    const float* __restrict__ xp0, const float* __restrict__ dw0, const float* __restrict__ db0,
    const float* __restrict__ Alog0,
    const float* __restrict__ cw1, const float* __restrict__ cb1,
    const float* __restrict__ xp1, const float* __restrict__ dw1, const float* __restrict__ db1,
    const float* __restrict__ Alog1) {
    extern __shared__ float sh[];
    float* su   = sh;                  // 35 x 256
    float* sxc  = su + 35 * C_;        // 32 x 256
    float* sxp  = sxc + 32 * C_;       // 24 x 256 ([o][k])
    float* sdwT = sxp + 24 * C_;       // 16 x 256 ([r][c])
    float* sdbl = sdwT + 16 * C_;      // 32 x 24

    int chk = blockIdx.x;
    int b = blockIdx.y >> 1, dir = blockIdx.y & 1;
    const float* cw = dir ? cw1 : cw0;
    const float* cb = dir ? cb1 : cb0;
    const float* xp = dir ? xp1 : xp0;
    const float* dw = dir ? dw1 : dw0;
    const float* db = dir ? db1 : db0;
    const float* Alog = dir ? Alog1 : Alog0;
    int tid = threadIdx.x;
    int q0 = chk * POS;

    for (int i = tid; i < 24 * C_; i += 256) sxp[i] = xp[i];
    for (int i = tid; i < 16 * C_; i += 256) {
        int c = i >> 4, r = i & 15;
        sdwT[r * C_ + c] = dw[i];
    }
    for (int i = tid; i < 35 * C_; i += 256) {
        int j = i >> 8, c2 = i & 255;
        int q = q0 - 3 + j;
        float v = 0.f;
        if (q >= 0) {
            int phys = dir ? (L_ - 1 - q) : q;
            v = g_uz[((size_t)(b * L_ + phys)) * 512 + c2];
        }
        su[j * C_ + c2] = v;
    }
    __syncthreads();

    {   // conv + silu
        int c = tid;
        float w0 = cw[c], w1 = cw[C_ + c], w2 = cw[2 * C_ + c], w3 = cw[3 * C_ + c];
        float cbv = cb[c];
        #pragma unroll
        for (int tp = 0; tp < POS; tp++) {
            float acc = cbv;
            acc = fmaf(w0, su[(tp + 0) * C_ + c], acc);
            acc = fmaf(w1, su[(tp + 1) * C_ + c], acc);
            acc = fmaf(w2, su[(tp + 2) * C_ + c], acc);
            acc = fmaf(w3, su[(tp + 3) * C_ + c], acc);
            sxc[tp * C_ + c] = siluf(acc);
        }
    }
    __syncthreads();

    {   // x_dbl: warp w handles positions w*4 .. w*4+3
        int w = tid >> 5, ln = tid & 31;
        #pragma unroll 1
        for (int ti = 0; ti < 4; ti++) {
            int tp = w * 4 + ti;
            float xv[8];
            #pragma unroll
            for (int j = 0; j < 8; j++) xv[j] = sxc[tp * C_ + ln + 32 * j];
            #pragma unroll 1
            for (int o = 0; o < 24; o++) {
                float acc = 0.f;
                #pragma unroll
                for (int j = 0; j < 8; j++)
                    acc = fmaf(xv[j], sxp[o * C_ + ln + 32 * j], acc);
                #pragma unroll
                for (int of = 16; of; of >>= 1)
                    acc += __shfl_down_sync(0xffffffffu, acc, of);
                if (ln == 0) sdbl[tp * 24 + o] = acc;
            }
        }
    }
    __syncthreads();

    if (tid < POS * 8) {
        int pos = tid >> 3, v = tid & 7;
        g_bc[dir][(size_t)(b * L_ + q0 + pos) * 8 + v] = sdbl[pos * 24 + 16 + v];
    }

    {   // dt_proj + softplus + chunk-local scan summary
        int c = tid;
        float dbv = db[c];
        float Av[4];
        #pragma unroll
        for (int n = 0; n < 4; n++) Av[n] = -__expf(Alog[c * 4 + n]);
        float h[4] = {0, 0, 0, 0}, aP[4] = {1, 1, 1, 1};
        #pragma unroll 1
        for (int pos = 0; pos < POS; pos++) {
            float val = dbv;
            #pragma unroll
            for (int r = 0; r < 16; r++)
                val = fmaf(sdbl[pos * 24 + r], sdwT[r * C_ + c], val);
            float dtv = (val > 20.f) ? val : log1pf(__expf(val));
            float uu = sxc[pos * C_ + c];
            g_dtu[dir][(size_t)(b * L_ + q0 + pos) * C_ + c] = make_float2(dtv, uu);
            float du = dtv * uu;
            #pragma unroll
            for (int n = 0; n < 4; n++) {
                float a = __expf(dtv * Av[n]);
                h[n] = fmaf(a, h[n], du * sdbl[pos * 24 + 16 + n]);
                aP[n] *= a;
            }
        }
        float* cs = g_cs[dir] + ((size_t)(b * NCH + chk) * C_ + c) * 8;
        #pragma unroll
        for (int n = 0; n < 4; n++) { cs[n] = aP[n]; cs[4 + n] = h[n]; }
    }
}

// ---------------- K4: scan phase 2 — warp-parallel chunk-state combine ---------
// One warp per (b,dir,c,n) chain of NCH=128 chunks; thread t owns chunks 4t..4t+3.
__global__ void scan2_kernel() {
    int bd  = blockIdx.x >> 7;             // 0..15 = b*2+dir
    int grp = blockIdx.x & 127;            // 8 chains per block
    int b = bd >> 1, dir = bd & 1;
    int w = threadIdx.x >> 5, t = threadIdx.x & 31;
    int chain = grp * 8 + w;               // 0..1023
    int c = chain >> 2, n = chain & 3;

    const float* cs = g_cs[dir] + ((size_t)(b * NCH) * C_ + c) * 8 + n;
    const size_t cstr = (size_t)C_ * 8;

    // batch loads for MLP
    float av[4], bv[4];
    #pragma unroll
    for (int j = 0; j < 4; j++) {
        size_t o = (size_t)(t * 4 + j) * cstr;
        av[j] = cs[o];
        bv[j] = cs[o + 4];
    }
    // within-thread exclusive prefixes + aggregate (A,B): h_out = A*h_in + B
    float Ae[4], Be[4];
    float A = 1.f, Bv = 0.f;
    #pragma unroll
    for (int j = 0; j < 4; j++) {
        Ae[j] = A; Be[j] = Bv;
        Bv = fmaf(av[j], Bv, bv[j]);
        A *= av[j];
    }
    // warp inclusive scan (compose with earlier segments)
    #pragma unroll
    for (int off = 1; off < 32; off <<= 1) {
        float Ap = __shfl_up_sync(0xffffffffu, A, off);
        float Bp = __shfl_up_sync(0xffffffffu, Bv, off);
        if (t >= off) {
            Bv = fmaf(A, Bp, Bv);
            A *= Ap;
        }
    }
    // exclusive: previous lane's inclusive value (h_in for this thread, from h0=0)
    float Bex = __shfl_up_sync(0xffffffffu, Bv, 1);
    if (t == 0) Bex = 0.f;

    float* h0 = g_h0[dir] + ((size_t)(b * NCH) * C_ + c) * 4 + n;
    const size_t hstr = (size_t)C_ * 4;
    #pragma unroll
    for (int j = 0; j < 4; j++)
        h0[(size_t)(t * 4 + j) * hstr] = fmaf(Ae[j], Bex, Be[j]);
}

// ---------------- K5: fused replay(f+b) + combine + silu(z) + LN ---------------
__global__ void scan3_fused_kernel(
    const float* __restrict__ Alog0, const float* __restrict__ Alog1,
    const float* __restrict__ D0, const float* __restrict__ D1,
    const float* __restrict__ nw, const float* __restrict__ nb) {
    __shared__ float sbcf[CHK * 8], sbcb[CHK * 8];
    __shared__ float ysm[CHK * C_];
    __shared__ float smu[CHK], srs[CHK];

    int ch = blockIdx.x;
    int b  = blockIdx.y;
    int c  = threadIdx.x;
    int chb = NCH - 1 - ch;
    int l0 = ch * CHK;

    {
        const float* gf = g_bc[0] + (size_t)(b * L_ + ch * CHK) * 8;
        const float* gb = g_bc[1] + (size_t)(b * L_ + chb * CHK) * 8;
        if (c < CHK * 8) { sbcf[c] = gf[c]; sbcb[c] = gb[c]; }
    }
    __syncthreads();

    // forward replay
    {
        float Av[4];
        #pragma unroll
        for (int n = 0; n < 4; n++) Av[n] = -__expf(Alog0[c * 4 + n]);
        float Dv = D0[c];
        const float* h0p = g_h0[0] + ((size_t)(b * NCH + ch) * C_ + c) * 4;
        float h[4];
        #pragma unroll
        for (int n = 0; n < 4; n++) h[n] = h0p[n];
        const float2* dtu = &g_dtu[0][(size_t)(b * L_ + l0) * C_ + c];
        #pragma unroll 4
        for (int t = 0; t < CHK; t++) {
            float2 v = dtu[(size_t)t * C_];
            float du = v.x * v.y;
            float y = v.y * Dv;
            #pragma unroll
            for (int n = 0; n < 4; n++) {
                float a = __expf(v.x * Av[n]);
                h[n] = fmaf(a, h[n], du * sbcf[t * 8 + n]);
                y = fmaf(h[n], sbcf[t * 8 + 4 + n], y);
            }
            ysm[t * C_ + c] = y;
        }
    }
    // backward replay: accumulates (same thread owns column c — no race)
    {
        float Av[4];
        #pragma unroll
        for (int n = 0; n < 4; n++) Av[n] = -__expf(Alog1[c * 4 + n]);
        float Dv = D1[c];
        const float* h0p = g_h0[1] + ((size_t)(b * NCH + chb) * C_ + c) * 4;
        float h[4];
        #pragma unroll
        for (int n = 0; n < 4; n++) h[n] = h0p[n];
        const float2* dtu = &g_dtu[1][(size_t)(b * L_ + chb * CHK) * C_ + c];
        #pragma unroll 4
        for (int tb = 0; tb < CHK; tb++) {
            float2 v = dtu[(size_t)tb * C_];
            float du = v.x * v.y;
            float y = v.y * Dv;
            #pragma unroll
            for (int n = 0; n < 4; n++) {
                float a = __expf(v.x * Av[n]);
                h[n] = fmaf(a, h[n], du * sbcb[tb * 8 + n]);
                y = fmaf(h[n], sbcb[tb * 8 + 4 + n], y);
            }
            ysm[(CHK - 1 - tb) * C_ + c] += y;
        }
    }
    // z-gate
    {
        const float* zp = &g_uz[(size_t)(b * L_ + l0) * 512 + 256 + c];
        #pragma unroll 4
        for (int t = 0; t < CHK; t++) {
            float z = zp[(size_t)t * 512];
            ysm[t * C_ + c] = 0.5f * ysm[t * C_ + c] * siluf(z);
        }
    }
    __syncthreads();
    // LN stats
    {
        int w = c >> 5, ln = c & 31;
        #pragma unroll
        for (int j = 0; j < 4; j++) {
            int t = w * 4 + j;
            float sm = 0.f, sq = 0.f;
            #pragma unroll
            for (int i = 0; i < 8; i++) {
                float v = ysm[t * C_ + ln + 32 * i];
                sm += v; sq += v * v;
            }
            #pragma unroll
            for (int o = 16; o; o >>= 1) {
                sm += __shfl_down_sync(0xffffffffu, sm, o);
                sq += __shfl_down_sync(0xffffffffu, sq, o);
            }
            if (ln == 0) {
                float mu = sm * (1.f / C_);
                float var = sq * (1.f / C_) - mu * mu;
                smu[t] = mu; srs[t] = rsqrtf(var + 1e-5f);
            }
        }
    }
    __syncthreads();
    {
        float wv = nw[c], bv = nb[c];
        #pragma unroll 4
        for (int t = 0; t < CHK; t++) {
            float v = ysm[t * C_ + c];
            g_h[(size_t)(b * L_ + l0 + t) * C_ + c] = (v - smu[t]) * srs[t] * wv + bv;
        }
    }
}

// ---------------- launch ---------------------------------------------------------
extern "C" void kernel_launch(void* const* d_in, const int* in_sizes, int n_in,
                              void* d_out, int out_size) {
    const float* x        = (const float*)d_in[0];
    const float* ln_w     = (const float*)d_in[1];
    const float* ln_b     = (const float*)d_in[2];
    const float* in_proj  = (const float*)d_in[3];
    const float* cw_f     = (const float*)d_in[4];
    const float* cb_f     = (const float*)d_in[5];
    const float* xp_f     = (const float*)d_in[6];
    const float* dw_f     = (const float*)d_in[7];
    const float* db_f     = (const float*)d_in[8];
    const float* Alog_f   = (const float*)d_in[9];
    const float* D_f      = (const float*)d_in[10];
    const float* cw_b     = (const float*)d_in[11];
    const float* cb_b     = (const float*)d_in[12];
    const float* xp_b     = (const float*)d_in[13];
    const float* dw_b     = (const float*)d_in[14];
    const float* db_b     = (const float*)d_in[15];
    const float* Alog_b   = (const float*)d_in[16];
    const float* D_b      = (const float*)d_in[17];
    const float* nrm_w    = (const float*)d_in[18];
    const float* nrm_b    = (const float*)d_in[19];
    const float* out_proj = (const float*)d_in[20];
    float* out = (float*)d_out;

    float* gh;  cudaGetSymbolAddress((void**)&gh,  g_h);
    float* guz; cudaGetSymbolAddress((void**)&guz, g_uz);

    const int gemm_smem = 4 * TILE_ELEM * 2;   // 73728 B
    cudaFuncSetAttribute(gemm_hmma, cudaFuncAttributeMaxDynamicSharedMemorySize, gemm_smem);
    const int conv_smem = (35 * C_ + 32 * C_ + 24 * C_ + 16 * C_ + 32 * 24) * 4;
    cudaFuncSetAttribute(convscan_kernel, cudaFuncAttributeMaxDynamicSharedMemorySize, conv_smem);

    // 1. LN (tiled transpose-load)
    ln_kernel<<<BN_ * 128, 256>>>(x, ln_w, ln_b);
    // 2. in_proj GEMM (32768 x 512) split-bf16 HMMA
    gemm_hmma<<<dim3(4, BL_ / 128), 256, gemm_smem>>>(gh, in_proj, guz, nullptr, 512, 0);
    // 3. conv + silu + x_proj + dt_proj + scan-phase1 (both directions)
    convscan_kernel<<<dim3(NCH, BN_ * 2), 256, conv_smem>>>(
        cw_f, cb_f, xp_f, dw_f, db_f, Alog_f,
        cw_b, cb_b, xp_b, dw_b, db_b, Alog_b);
    // 4. scan phase 2 (warp-parallel Hillis-Steele over chunks)
    scan2_kernel<<<2048, 256>>>();
    // 5. fused replay + combine + silu(z) + LN
    scan3_fused_kernel<<<dim3(NCH, BN_), 256>>>(Alog_f, Alog_b, D_f, D_b, nrm_w, nrm_b);
    // 6. out_proj GEMM + residual + transposed write (fused epilogue)
    gemm_hmma<<<dim3(2, BL_ / 128), 256, gemm_smem>>>(gh, out_proj, out, x, 256, 1);
}

// round 7
// speedup vs baseline: 5.2695x; 1.1115x over previous
#include <cuda_runtime.h>
#include <cuda_bf16.h>
#include <cuda_fp16.h>
#include <math.h>
#include <stdint.h>

#define BN_ 8
#define C_ 256
#define L_ 4096
#define BL_ (BN_*L_)
#define NCH 128
#define CHK 32
#define POS 32

// ---------------- scratch (device globals) -----------------------------------
__device__ float   g_h  [BL_*C_];            // LN output / normalized y (reused)
__device__ float   g_u  [BL_*C_];            // in_proj u
__device__ float   g_z  [BL_*C_];            // in_proj z
__device__ __half2 g_dtu[2][(size_t)BL_*C_]; // (dt, u) fp16 pairs, dir space
__device__ float   g_bc [2][BL_*8];          // Bc[0:4], Cc[4:8] dir space
__device__ float   g_cs [2][BN_*NCH*C_*8];   // chunk summaries: interleaved (aP,h) float2 at [c*4+n]
__device__ float   g_h0 [2][BN_*NCH*C_*4];   // corrected chunk initial states
__device__ __nv_bfloat16 g_wih[512*256], g_wil[512*256];  // in_proj hi/lo
__device__ __nv_bfloat16 g_woh[256*256], g_wol[256*256];  // out_proj hi/lo

// ---------------- helpers -----------------------------------------------------
__device__ __forceinline__ float siluf(float x) { return x / (1.f + __expf(-x)); }

__device__ __forceinline__ uint32_t pkbf(__nv_bfloat16 a, __nv_bfloat16 b) {
    __nv_bfloat162 t = __halves2bfloat162(a, b);
    return *(uint32_t*)&t;
}

__device__ __forceinline__ void mma16816(float* c, const uint32_t* a, const uint32_t* b) {
    asm volatile(
        "mma.sync.aligned.m16n8k16.row.col.f32.bf16.bf16.f32 "
        "{%0,%1,%2,%3}, {%4,%5,%6,%7}, {%8,%9}, {%0,%1,%2,%3};"
        : "+f"(c[0]), "+f"(c[1]), "+f"(c[2]), "+f"(c[3])
        : "r"(a[0]), "r"(a[1]), "r"(a[2]), "r"(a[3]), "r"(b[0]), "r"(b[1]));
}

// ---------------- K0: weight pre-split (fp32 -> bf16 hi/lo) --------------------
__global__ void wprep_kernel(const float* __restrict__ W,
                             __nv_bfloat16* __restrict__ Wh,
                             __nv_bfloat16* __restrict__ Wl, int n) {
    int i = blockIdx.x * 256 + threadIdx.x;
    if (i < n) {
        float v = W[i];
        __nv_bfloat16 h = __float2bfloat16(v);
        Wh[i] = h;
        Wl[i] = __float2bfloat16(v - __bfloat162float(h));
    }
}

// ---------------- K1: tiled transpose + LayerNorm -----------------------------
__global__ void ln_kernel(const float* __restrict__ x,
                          const float* __restrict__ wgt,
                          const float* __restrict__ bia) {
    __shared__ float s[C_][33];
    __shared__ float smu[32], srs[32];
    int b = blockIdx.x >> 7;
    int l0 = (blockIdx.x & 127) * 32;
    int tid = threadIdx.x, w = tid >> 5, ln = tid & 31;

    for (int c = w; c < C_; c += 8)
        s[c][ln] = x[((size_t)b * C_ + c) * L_ + l0 + ln];
    __syncthreads();

    #pragma unroll
    for (int j = 0; j < 4; j++) {
        int l = w * 4 + j;
        float sm = 0.f, sq = 0.f;
        #pragma unroll
        for (int i = 0; i < 8; i++) {
            float v = s[ln + 32 * i][l];
            sm += v; sq += v * v;
        }
        #pragma unroll
        for (int o = 16; o; o >>= 1) {
            sm += __shfl_down_sync(0xffffffffu, sm, o);
            sq += __shfl_down_sync(0xffffffffu, sq, o);
        }
        if (ln == 0) {
            float mu = sm * (1.f / C_);
            float var = sq * (1.f / C_) - mu * mu;
            smu[l] = mu; srs[l] = rsqrtf(var + 1e-5f);
        }
    }
    __syncthreads();

    int c = tid;
    float wv = wgt[c], bv = bia[c];
    for (int l = 0; l < 32; l++) {
        float v = s[c][l];
        g_h[((size_t)b * L_ + l0 + l) * C_ + c] = (v - smu[l]) * srs[l] * wv + bv;
    }
}

// ---------------- K2: split-bf16 HMMA GEMM (pre-split W) -----------------------
// mode 0: in_proj — write u (n<256) / z (n>=256) split arrays
// mode 1: out_proj — transposed write + residual
#define SR 72
#define TILE_ELEM (128 * SR)
__global__ void __launch_bounds__(256, 2) gemm_hmma(
    const float* __restrict__ A,
    const __nv_bfloat16* __restrict__ Wh, const __nv_bfloat16* __restrict__ Wl,
    float* __restrict__ out0, float* __restrict__ out1,
    const float* __restrict__ xres, int mode) {
    extern __shared__ __nv_bfloat16 sm[];
    __nv_bfloat16* sAh = sm;
    __nv_bfloat16* sAl = sAh + TILE_ELEM;
    __nv_bfloat16* sBh = sAl + TILE_ELEM;
    __nv_bfloat16* sBl = sBh + TILE_ELEM;

    int tid = threadIdx.x, wid = tid >> 5, lid = tid & 31;
    int g = lid >> 2, t = lid & 3;
    int warp_m = wid & 1, warp_n = wid >> 1;
    int n0 = blockIdx.x * 128, m0 = blockIdx.y * 128;

    float acc[4][4][4] = {};

    int frow = tid >> 1;
    int fkh = (tid & 1) * 32;
    const float* Abase = A + (size_t)(m0 + frow) * 256 + fkh;
    const __nv_bfloat16* Whb = Wh + (size_t)(n0 + frow) * 256 + fkh;
    const __nv_bfloat16* Wlb = Wl + (size_t)(n0 + frow) * 256 + fkh;

    for (int kc = 0; kc < 4; kc++) {
        __syncthreads();
        {   // A tile: convert fp32 -> hi/lo
            const float* src = Abase + kc * 64;
            __nv_bfloat16* dh = sAh + frow * SR + fkh;
            __nv_bfloat16* dl = sAl + frow * SR + fkh;
            #pragma unroll
            for (int j = 0; j < 8; j++) {
                float4 v = *(const float4*)(src + j * 4);
                __nv_bfloat16 h0 = __float2bfloat16(v.x), h1 = __float2bfloat16(v.y);
                __nv_bfloat16 h2 = __float2bfloat16(v.z), h3 = __float2bfloat16(v.w);
                __nv_bfloat16 e0 = __float2bfloat16(v.x - __bfloat162float(h0));
                __nv_bfloat16 e1 = __float2bfloat16(v.y - __bfloat162float(h1));
                __nv_bfloat16 e2 = __float2bfloat16(v.z - __bfloat162float(h2));
                __nv_bfloat16 e3 = __float2bfloat16(v.w - __bfloat162float(h3));
                *(uint2*)(dh + j * 4) = make_uint2(pkbf(h0, h1), pkbf(h2, h3));
                *(uint2*)(dl + j * 4) = make_uint2(pkbf(e0, e1), pkbf(e2, e3));
            }
        }
        {   // B tile: plain vector copies of pre-split weights
            __nv_bfloat16* dh = sBh + frow * SR + fkh;
            __nv_bfloat16* dl = sBl + frow * SR + fkh;
            #pragma unroll
            for (int j = 0; j < 4; j++) {
                *(uint4*)(dh + j * 8) = *(const uint4*)(Whb + kc * 64 + j * 8);
                *(uint4*)(dl + j * 8) = *(const uint4*)(Wlb + kc * 64 + j * 8);
            }
        }
        __syncthreads();

        #pragma unroll
        for (int ks = 0; ks < 4; ks++) {
            int c0 = ks * 16 + t * 2;
            uint32_t bh[4][2], bl[4][2];
            #pragma unroll
            for (int ni = 0; ni < 4; ni++) {
                int n = warp_n * 32 + ni * 8 + g;
                bh[ni][0] = *(const uint32_t*)&sBh[n * SR + c0];
                bh[ni][1] = *(const uint32_t*)&sBh[n * SR + c0 + 8];
                bl[ni][0] = *(const uint32_t*)&sBl[n * SR + c0];
                bl[ni][1] = *(const uint32_t*)&sBl[n * SR + c0 + 8];
            }
            #pragma unroll
            for (int mi = 0; mi < 4; mi++) {
                int r = warp_m * 64 + mi * 16 + g;
                uint32_t ah[4], al[4];
                ah[0] = *(const uint32_t*)&sAh[r * SR + c0];
                ah[1] = *(const uint32_t*)&sAh[(r + 8) * SR + c0];
                ah[2] = *(const uint32_t*)&sAh[r * SR + c0 + 8];
                ah[3] = *(const uint32_t*)&sAh[(r + 8) * SR + c0 + 8];
                al[0] = *(const uint32_t*)&sAl[r * SR + c0];
                al[1] = *(const uint32_t*)&sAl[(r + 8) * SR + c0];
                al[2] = *(const uint32_t*)&sAl[r * SR + c0 + 8];
                al[3] = *(const uint32_t*)&sAl[(r + 8) * SR + c0 + 8];
                #pragma unroll
                for (int ni = 0; ni < 4; ni++) {
                    mma16816(acc[mi][ni], ah, bh[ni]);
                    mma16816(acc[mi][ni], ah, bl[ni]);
                    mma16816(acc[mi][ni], al, bh[ni]);
                }
            }
        }
    }

    if (mode == 0) {
        float* dst = (n0 < 256) ? out0 : out1;
        int nb = n0 & 255;
        #pragma unroll
        for (int mi = 0; mi < 4; mi++) {
            int r = m0 + warp_m * 64 + mi * 16 + g;
            #pragma unroll
            for (int ni = 0; ni < 4; ni++) {
                int n = nb + warp_n * 32 + ni * 8 + t * 2;
                *(float2*)&dst[(size_t)r * 256 + n] = make_float2(acc[mi][ni][0], acc[mi][ni][1]);
                *(float2*)&dst[(size_t)(r + 8) * 256 + n] = make_float2(acc[mi][ni][2], acc[mi][ni][3]);
            }
        }
    } else {
        int bb = m0 >> 12, l0 = m0 & 4095;
        #pragma unroll
        for (int mi = 0; mi < 4; mi++) {
            int l = l0 + warp_m * 64 + mi * 16 + g;
            #pragma unroll
            for (int ni = 0; ni < 4; ni++) {
                int ch = n0 + warp_n * 32 + ni * 8 + t * 2;
                size_t o0 = ((size_t)bb * C_ + ch) * L_ + l;
                out0[o0]          = acc[mi][ni][0] + xres[o0];
                out0[o0 + L_]     = acc[mi][ni][1] + xres[o0 + L_];
                out0[o0 + 8]      = acc[mi][ni][2] + xres[o0 + 8];
                out0[o0 + L_ + 8] = acc[mi][ni][3] + xres[o0 + L_ + 8];
            }
        }
    }
}

// ---------------- K3: conv + silu + x_proj + dt_proj + scan-phase1 ------------
__global__ void convscan_kernel(
    const float* __restrict__ cw0, const float* __restrict__ cb0,
    const float* __restrict__ xp0, const float* __restrict__ dw0, const float* __restrict__ db0,
    const float* __restrict__ Alog0,
    const float* __restrict__ cw1, const float* __restrict__ cb1,
    const float* __restrict__ xp1, const float* __restrict__ dw1, const float* __restrict__ db1,
    const float* __restrict__ Alog1) {
    extern __shared__ float sh[];
    float* su   = sh;                  // 35 x 256
    float* sxc  = su + 35 * C_;        // 32 x 256
    float* sxp  = sxc + 32 * C_;       // 24 x 256 ([o][k])
    float* sdwT = sxp + 24 * C_;       // 16 x 256 ([r][c])
    float* sdbl = sdwT + 16 * C_;      // 32 x 24

    int chk = blockIdx.x;
    int b = blockIdx.y >> 1, dir = blockIdx.y & 1;
    const float* cw = dir ? cw1 : cw0;
    const float* cb = dir ? cb1 : cb0;
    const float* xp = dir ? xp1 : xp0;
    const float* dw = dir ? dw1 : dw0;
    const float* db = dir ? db1 : db0;
    const float* Alog = dir ? Alog1 : Alog0;
    int tid = threadIdx.x;
    int q0 = chk * POS;

    for (int i = tid; i < 24 * C_; i += 256) sxp[i] = xp[i];
    for (int i = tid; i < 16 * C_; i += 256) {
        int c = i >> 4, r = i & 15;
        sdwT[r * C_ + c] = dw[i];
    }
    for (int i = tid; i < 35 * C_; i += 256) {
        int j = i >> 8, c2 = i & 255;
        int q = q0 - 3 + j;
        float v = 0.f;
        if (q >= 0) {
            int phys = dir ? (L_ - 1 - q) : q;
            v = g_u[(size_t)(b * L_ + phys) * C_ + c2];
        }
        su[j * C_ + c2] = v;
    }
    __syncthreads();

    {   // conv + silu
        int c = tid;
        float w0 = cw[c], w1 = cw[C_ + c], w2 = cw[2 * C_ + c], w3 = cw[3 * C_ + c];
        float cbv = cb[c];
        #pragma unroll
        for (int tp = 0; tp < POS; tp++) {
            float acc = cbv;
            acc = fmaf(w0, su[(tp + 0) * C_ + c], acc);
            acc = fmaf(w1, su[(tp + 1) * C_ + c], acc);
            acc = fmaf(w2, su[(tp + 2) * C_ + c], acc);
            acc = fmaf(w3, su[(tp + 3) * C_ + c], acc);
            sxc[tp * C_ + c] = siluf(acc);
        }
    }
    __syncthreads();

    {   // x_dbl: warp w handles positions w*4 .. w*4+3
        int w = tid >> 5, ln = tid & 31;
        #pragma unroll 1
        for (int ti = 0; ti < 4; ti++) {
            int tp = w * 4 + ti;
            float xv[8];
            #pragma unroll
            for (int j = 0; j < 8; j++) xv[j] = sxc[tp * C_ + ln + 32 * j];
            #pragma unroll 1
            for (int o = 0; o < 24; o++) {
                float acc = 0.f;
                #pragma unroll
                for (int j = 0; j < 8; j++)
                    acc = fmaf(xv[j], sxp[o * C_ + ln + 32 * j], acc);
                #pragma unroll
                for (int of = 16; of; of >>= 1)
                    acc += __shfl_down_sync(0xffffffffu, acc, of);
                if (ln == 0) sdbl[tp * 24 + o] = acc;
            }
        }
    }
    __syncthreads();

    if (tid < POS * 8) {
        int pos = tid >> 3, v = tid & 7;
        g_bc[dir][(size_t)(b * L_ + q0 + pos) * 8 + v] = sdbl[pos * 24 + 16 + v];
    }

    {   // dt_proj + softplus + chunk-local scan summary (fp16-consistent)
        int c = tid;
        float dbv = db[c];
        float Av[4];
        #pragma unroll
        for (int n = 0; n < 4; n++) Av[n] = -__expf(Alog[c * 4 + n]);
        float h[4] = {0, 0, 0, 0}, aP[4] = {1, 1, 1, 1};
        #pragma unroll 1
        for (int pos = 0; pos < POS; pos++) {
            float val = dbv;
            #pragma unroll
            for (int r = 0; r < 16; r++)
                val = fmaf(sdbl[pos * 24 + r], sdwT[r * C_ + c], val);
            float dtv = (val > 20.f) ? val : log1pf(__expf(val));
            float uu = sxc[pos * C_ + c];
            __half2 p = __floats2half2_rn(dtv, uu);
            g_dtu[dir][(size_t)(b * L_ + q0 + pos) * C_ + c] = p;
            float2 q = __half22float2(p);     // use quantized values for consistency
            float du = q.x * q.y;
            #pragma unroll
            for (int n = 0; n < 4; n++) {
                float a = __expf(q.x * Av[n]);
                h[n] = fmaf(a, h[n], du * sdbl[pos * 24 + 16 + n]);
                aP[n] *= a;
            }
        }
        float* cs = g_cs[dir] + ((size_t)(b * NCH + chk) * C_ + c) * 8;
        #pragma unroll
        for (int n = 0; n < 4; n++) { cs[n * 2] = aP[n]; cs[n * 2 + 1] = h[n]; }
    }
}

// ---------------- K4: scan phase 2 — coalesced serial chain per thread ---------
__global__ void scan2_kernel() {
    int tg = blockIdx.x * 256 + threadIdx.x;   // 16384 threads
    int bd = tg >> 10;
    int cn = tg & 1023;
    int b = bd >> 1, dir = bd & 1;
    const float2* cs = (const float2*)(g_cs[dir] + (size_t)b * NCH * C_ * 8) + cn;
    float* h0 = g_h0[dir] + (size_t)b * NCH * C_ * 4 + cn;
    float B = 0.f;
    #pragma unroll 8
    for (int ch = 0; ch < NCH; ch++) {
        float2 v = cs[(size_t)ch * 1024];
        h0[(size_t)ch * 1024] = B;
        B = fmaf(v.x, B, v.y);
    }
}

// ---------------- K5: fused replay(f+b) + combine + silu(z) + LN ---------------
__global__ void scan3_fused_kernel(
    const float* __restrict__ Alog0, const float* __restrict__ Alog1,
    const float* __restrict__ D0, const float* __restrict__ D1,
    const float* __restrict__ nw, const float* __restrict__ nb) {
    __shared__ float sbcf[CHK * 8], sbcb[CHK * 8];
    __shared__ float ysm[CHK * C_];
    __shared__ float smu[CHK], srs[CHK];

    int ch = blockIdx.x;
    int b  = blockIdx.y;
    int c  = threadIdx.x;
    int chb = NCH - 1 - ch;
    int l0 = ch * CHK;

    {
        const float* gf = g_bc[0] + (size_t)(b * L_ + ch * CHK) * 8;
        const float* gb = g_bc[1] + (size_t)(b * L_ + chb * CHK) * 8;
        if (c < CHK * 8) { sbcf[c] = gf[c]; sbcb[c] = gb[c]; }
    }
    __syncthreads();

    // forward replay
    {
        float Av[4];
        #pragma unroll
        for (int n = 0; n < 4; n++) Av[n] = -__expf(Alog0[c * 4 + n]);
        float Dv = D0[c];
        const float* h0p = g_h0[0] + ((size_t)(b * NCH + ch) * C_ + c) * 4;
        float h[4];
        #pragma unroll
        for (int n = 0; n < 4; n++) h[n] = h0p[n];
        const __half2* dtu = &g_dtu[0][(size_t)(b * L_ + l0) * C_ + c];
        #pragma unroll 4
        for (int t = 0; t < CHK; t++) {
            float2 v = __half22float2(dtu[(size_t)t * C_]);
            float du = v.x * v.y;
            float y = v.y * Dv;
            #pragma unroll
            for (int n = 0; n < 4; n++) {
                float a = __expf(v.x * Av[n]);
                h[n] = fmaf(a, h[n], du * sbcf[t * 8 + n]);
                y = fmaf(h[n], sbcf[t * 8 + 4 + n], y);
            }
            ysm[t * C_ + c] = y;
        }
    }
    // backward replay: accumulates (same thread owns column c — no race)
    {
        float Av[4];
        #pragma unroll
        for (int n = 0; n < 4; n++) Av[n] = -__expf(Alog1[c * 4 + n]);
        float Dv = D1[c];
        const float* h0p = g_h0[1] + ((size_t)(b * NCH + chb) * C_ + c) * 4;
        float h[4];
        #pragma unroll
        for (int n = 0; n < 4; n++) h[n] = h0p[n];
        const __half2* dtu = &g_dtu[1][(size_t)(b * L_ + chb * CHK) * C_ + c];
        #pragma unroll 4
        for (int tb = 0; tb < CHK; tb++) {
            float2 v = __half22float2(dtu[(size_t)tb * C_]);
            float du = v.x * v.y;
            float y = v.y * Dv;
            #pragma unroll
            for (int n = 0; n < 4; n++) {
                float a = __expf(v.x * Av[n]);
                h[n] = fmaf(a, h[n], du * sbcb[tb * 8 + n]);
                y = fmaf(h[n], sbcb[tb * 8 + 4 + n], y);
            }
            ysm[(CHK - 1 - tb) * C_ + c] += y;
        }
    }
    // z-gate (now coalesced)
    {
        const float* zp = &g_z[(size_t)(b * L_ + l0) * C_ + c];
        #pragma unroll 4
        for (int t = 0; t < CHK; t++) {
            float z = zp[(size_t)t * C_];
            ysm[t * C_ + c] = 0.5f * ysm[t * C_ + c] * siluf(z);
        }
    }
    __syncthreads();
    // LN stats
    {
        int w = c >> 5, ln = c & 31;
        #pragma unroll
        for (int j = 0; j < 4; j++) {
            int t = w * 4 + j;
            float sm = 0.f, sq = 0.f;
            #pragma unroll
            for (int i = 0; i < 8; i++) {
                float v = ysm[t * C_ + ln + 32 * i];
                sm += v; sq += v * v;
            }
            #pragma unroll
            for (int o = 16; o; o >>= 1) {
                sm += __shfl_down_sync(0xffffffffu, sm, o);
                sq += __shfl_down_sync(0xffffffffu, sq, o);
            }
            if (ln == 0) {
                float mu = sm * (1.f / C_);
                float var = sq * (1.f / C_) - mu * mu;
                smu[t] = mu; srs[t] = rsqrtf(var + 1e-5f);
            }
        }
    }
    __syncthreads();
    {
        float wv = nw[c], bv = nb[c];
        #pragma unroll 4
        for (int t = 0; t < CHK; t++) {
            float v = ysm[t * C_ + c];
            g_h[(size_t)(b * L_ + l0 + t) * C_ + c] = (v - smu[t]) * srs[t] * wv + bv;
        }
    }
}

// ---------------- launch ---------------------------------------------------------
extern "C" void kernel_launch(void* const* d_in, const int* in_sizes, int n_in,
                              void* d_out, int out_size) {
    const float* x        = (const float*)d_in[0];
    const float* ln_w     = (const float*)d_in[1];
    const float* ln_b     = (const float*)d_in[2];
    const float* in_proj  = (const float*)d_in[3];
    const float* cw_f     = (const float*)d_in[4];
    const float* cb_f     = (const float*)d_in[5];
    const float* xp_f     = (const float*)d_in[6];
    const float* dw_f     = (const float*)d_in[7];
    const float* db_f     = (const float*)d_in[8];
    const float* Alog_f   = (const float*)d_in[9];
    const float* D_f      = (const float*)d_in[10];
    const float* cw_b     = (const float*)d_in[11];
    const float* cb_b     = (const float*)d_in[12];
    const float* xp_b     = (const float*)d_in[13];
    const float* dw_b     = (const float*)d_in[14];
    const float* db_b     = (const float*)d_in[15];
    const float* Alog_b   = (const float*)d_in[16];
    const float* D_b      = (const float*)d_in[17];
    const float* nrm_w    = (const float*)d_in[18];
    const float* nrm_b    = (const float*)d_in[19];
    const float* out_proj = (const float*)d_in[20];
    float* out = (float*)d_out;

    float* gh;  cudaGetSymbolAddress((void**)&gh,  g_h);
    float* gu;  cudaGetSymbolAddress((void**)&gu,  g_u);
    float* gz;  cudaGetSymbolAddress((void**)&gz,  g_z);
    __nv_bfloat16 *wih, *wil, *woh, *wol;
    cudaGetSymbolAddress((void**)&wih, g_wih);
    cudaGetSymbolAddress((void**)&wil, g_wil);
    cudaGetSymbolAddress((void**)&woh, g_woh);
    cudaGetSymbolAddress((void**)&wol, g_wol);

    const int gemm_smem = 4 * TILE_ELEM * 2;   // 73728 B
    cudaFuncSetAttribute(gemm_hmma, cudaFuncAttributeMaxDynamicSharedMemorySize, gemm_smem);
    const int conv_smem = (35 * C_ + 32 * C_ + 24 * C_ + 16 * C_ + 32 * 24) * 4;
    cudaFuncSetAttribute(convscan_kernel, cudaFuncAttributeMaxDynamicSharedMemorySize, conv_smem);

    // 0. pre-split weights to bf16 hi/lo
    wprep_kernel<<<512, 256>>>(in_proj, wih, wil, 512 * 256);
    wprep_kernel<<<256, 256>>>(out_proj, woh, wol, 256 * 256);
    // 1. LN (tiled transpose-load)
    ln_kernel<<<BN_ * 128, 256>>>(x, ln_w, ln_b);
    // 2. in_proj GEMM (32768 x 512) -> u/z split
    gemm_hmma<<<dim3(4, BL_ / 128), 256, gemm_smem>>>(gh, wih, wil, gu, gz, nullptr, 0);
    // 3. conv + silu + x_proj + dt_proj + scan-phase1 (both directions)
    convscan_kernel<<<dim3(NCH, BN_ * 2), 256, conv_smem>>>(
        cw_f, cb_f, xp_f, dw_f, db_f, Alog_f,
        cw_b, cb_b, xp_b, dw_b, db_b, Alog_b);
    // 4. scan phase 2 (coalesced serial chains)
    scan2_kernel<<<64, 256>>>();
    // 5. fused replay + combine + silu(z) + LN
    scan3_fused_kernel<<<dim3(NCH, BN_), 256>>>(Alog_f, Alog_b, D_f, D_b, nrm_w, nrm_b);
    // 6. out_proj GEMM + residual + transposed write (fused epilogue)
    gemm_hmma<<<dim3(2, BL_ / 128), 256, gemm_smem>>>(gh, woh, wol, out, nullptr, x, 1);
}

// round 8
// speedup vs baseline: 5.6902x; 1.0799x over previous
#include <cuda_runtime.h>
#include <cuda_bf16.h>
#include <cuda_fp16.h>
#include <math.h>
#include <stdint.h>

#define BN_ 8
#define C_ 256
#define L_ 4096
#define BL_ (BN_*L_)
#define NCH 128
#define CHK 32
#define POS 32

// ---------------- scratch (device globals) -----------------------------------
__device__ __nv_bfloat16 g_ah[BL_*C_], g_al[BL_*C_];  // activation hi/lo (LN out, then y-norm)
__device__ float   g_u  [BL_*C_];            // in_proj u
__device__ float   g_z  [BL_*C_];            // in_proj z
__device__ __half2 g_dtu[2][(size_t)BL_*C_]; // (dt, u) fp16 pairs, dir space
__device__ float   g_bc [2][BL_*8];          // Bc[0:4], Cc[4:8] dir space
__device__ float   g_cs [2][BN_*NCH*C_*8];   // chunk summaries: (aP,h) float2 at [c*4+n]
__device__ float   g_h0 [2][BN_*NCH*C_*4];   // corrected chunk initial states
__device__ __nv_bfloat16 g_wih[512*256], g_wil[512*256];  // in_proj hi/lo
__device__ __nv_bfloat16 g_woh[256*256], g_wol[256*256];  // out_proj hi/lo

// ---------------- helpers -----------------------------------------------------
__device__ __forceinline__ float siluf(float x) { return x / (1.f + __expf(-x)); }

__device__ __forceinline__ uint32_t smem_u32(const void* p) {
    uint32_t a;
    asm("{ .reg .u64 t; cvta.to.shared.u64 t, %1; cvt.u32.u64 %0, t; }" : "=r"(a) : "l"(p));
    return a;
}

__device__ __forceinline__ void mma16816(float* c, const uint32_t* a, const uint32_t* b) {
    asm volatile(
        "mma.sync.aligned.m16n8k16.row.col.f32.bf16.bf16.f32 "
        "{%0,%1,%2,%3}, {%4,%5,%6,%7}, {%8,%9}, {%0,%1,%2,%3};"
        : "+f"(c[0]), "+f"(c[1]), "+f"(c[2]), "+f"(c[3])
        : "r"(a[0]), "r"(a[1]), "r"(a[2]), "r"(a[3]), "r"(b[0]), "r"(b[1]));
}

__device__ __forceinline__ void ldsm4(uint32_t* r, uint32_t addr) {
    asm volatile("ldmatrix.sync.aligned.m8n8.x4.shared.b16 {%0,%1,%2,%3}, [%4];"
        : "=r"(r[0]), "=r"(r[1]), "=r"(r[2]), "=r"(r[3]) : "r"(addr));
}

// ---------------- K0: weight pre-split (fp32 -> bf16 hi/lo) --------------------
__global__ void wprep_kernel(const float* __restrict__ W,
                             __nv_bfloat16* __restrict__ Wh,
                             __nv_bfloat16* __restrict__ Wl, int n) {
    int i = blockIdx.x * 256 + threadIdx.x;
    if (i < n) {
        float v = W[i];
        __nv_bfloat16 h = __float2bfloat16(v);
        Wh[i] = h;
        Wl[i] = __float2bfloat16(v - __bfloat162float(h));
    }
}

// ---------------- K1: tiled transpose + LayerNorm -> bf16 hi/lo ----------------
__global__ void ln_kernel(const float* __restrict__ x,
                          const float* __restrict__ wgt,
                          const float* __restrict__ bia) {
    __shared__ float s[C_][33];
    __shared__ float smu[32], srs[32];
    int b = blockIdx.x >> 7;
    int l0 = (blockIdx.x & 127) * 32;
    int tid = threadIdx.x, w = tid >> 5, ln = tid & 31;

    for (int c = w; c < C_; c += 8)
        s[c][ln] = x[((size_t)b * C_ + c) * L_ + l0 + ln];
    __syncthreads();

    #pragma unroll
    for (int j = 0; j < 4; j++) {
        int l = w * 4 + j;
        float sm = 0.f, sq = 0.f;
        #pragma unroll
        for (int i = 0; i < 8; i++) {
            float v = s[ln + 32 * i][l];
            sm += v; sq += v * v;
        }
        #pragma unroll
        for (int o = 16; o; o >>= 1) {
            sm += __shfl_down_sync(0xffffffffu, sm, o);
            sq += __shfl_down_sync(0xffffffffu, sq, o);
        }
        if (ln == 0) {
            float mu = sm * (1.f / C_);
            float var = sq * (1.f / C_) - mu * mu;
            smu[l] = mu; srs[l] = rsqrtf(var + 1e-5f);
        }
    }
    __syncthreads();

    int c = tid;
    float wv = wgt[c], bv = bia[c];
    for (int l = 0; l < 32; l++) {
        float v = (s[c][l] - smu[l]) * srs[l] * wv + bv;
        __nv_bfloat16 h = __float2bfloat16(v);
        size_t o = ((size_t)b * L_ + l0 + l) * C_ + c;
        g_ah[o] = h;
        g_al[o] = __float2bfloat16(v - __bfloat162float(h));
    }
}

// ---------------- K2: split-bf16 HMMA GEMM (ldmatrix, pre-split A & W) ---------
// mode 0: in_proj — write u (n<256) / z (n>=256)
// mode 1: out_proj — transposed write + residual
#define SR 72
#define TILE_ELEM (128 * SR)
__global__ void __launch_bounds__(256, 2) gemm_hmma(
    const __nv_bfloat16* __restrict__ Ah, const __nv_bfloat16* __restrict__ Al,
    const __nv_bfloat16* __restrict__ Wh, const __nv_bfloat16* __restrict__ Wl,
    float* __restrict__ out0, float* __restrict__ out1,
    const float* __restrict__ xres, int mode) {
    extern __shared__ __nv_bfloat16 sm[];
    __nv_bfloat16* sAh = sm;
    __nv_bfloat16* sAl = sAh + TILE_ELEM;
    __nv_bfloat16* sBh = sAl + TILE_ELEM;
    __nv_bfloat16* sBl = sBh + TILE_ELEM;

    int tid = threadIdx.x, wid = tid >> 5, lid = tid & 31;
    int g = lid >> 2, t = lid & 3;
    int warp_m = wid & 1, warp_n = wid >> 1;
    int n0 = blockIdx.x * 128, m0 = blockIdx.y * 128;

    float acc[4][4][4] = {};

    int frow = tid >> 1;
    int fkh = (tid & 1) * 32;
    const __nv_bfloat16* Ahb = Ah + (size_t)(m0 + frow) * 256 + fkh;
    const __nv_bfloat16* Alb = Al + (size_t)(m0 + frow) * 256 + fkh;
    const __nv_bfloat16* Whb = Wh + (size_t)(n0 + frow) * 256 + fkh;
    const __nv_bfloat16* Wlb = Wl + (size_t)(n0 + frow) * 256 + fkh;

    // ldmatrix per-lane byte offsets
    uint32_t sAh_b = smem_u32(sAh), sAl_b = smem_u32(sAl);
    uint32_t sBh_b = smem_u32(sBh), sBl_b = smem_u32(sBl);
    uint32_t aoff = ((warp_m * 64 + (lid & 15)) * SR + (lid >> 4) * 8) * 2;
    int bn = (lid & 7) + ((lid >> 4) << 3);
    uint32_t boff = ((warp_n * 32 + bn) * SR + ((lid >> 3) & 1) * 8) * 2;

    for (int kc = 0; kc < 4; kc++) {
        __syncthreads();
        {   // fill tiles: pure vector copies
            __nv_bfloat16* dAh = sAh + frow * SR + fkh;
            __nv_bfloat16* dAl = sAl + frow * SR + fkh;
            __nv_bfloat16* dBh = sBh + frow * SR + fkh;
            __nv_bfloat16* dBl = sBl + frow * SR + fkh;
            #pragma unroll
            for (int j = 0; j < 4; j++) {
                *(uint4*)(dAh + j * 8) = *(const uint4*)(Ahb + kc * 64 + j * 8);
                *(uint4*)(dAl + j * 8) = *(const uint4*)(Alb + kc * 64 + j * 8);
                *(uint4*)(dBh + j * 8) = *(const uint4*)(Whb + kc * 64 + j * 8);
                *(uint4*)(dBl + j * 8) = *(const uint4*)(Wlb + kc * 64 + j * 8);
            }
        }
        __syncthreads();

        #pragma unroll
        for (int ks = 0; ks < 4; ks++) {
            uint32_t bh[2][4], bl[2][4];
            ldsm4(bh[0], sBh_b + boff + ks * 32);
            ldsm4(bh[1], sBh_b + boff + 16 * SR * 2 + ks * 32);
            ldsm4(bl[0], sBl_b + boff + ks * 32);
            ldsm4(bl[1], sBl_b + boff + 16 * SR * 2 + ks * 32);
            #pragma unroll
            for (int mi = 0; mi < 4; mi++) {
                uint32_t ah[4], al[4];
                ldsm4(ah, sAh_b + aoff + mi * 16 * SR * 2 + ks * 32);
                ldsm4(al, sAl_b + aoff + mi * 16 * SR * 2 + ks * 32);
                #pragma unroll
                for (int ni = 0; ni < 4; ni++) {
                    const uint32_t* bph = &bh[ni >> 1][(ni & 1) * 2];
                    const uint32_t* bpl = &bl[ni >> 1][(ni & 1) * 2];
                    mma16816(acc[mi][ni], ah, bph);
                    mma16816(acc[mi][ni], ah, bpl);
                    mma16816(acc[mi][ni], al, bph);
                }
            }
        }
    }

    if (mode == 0) {
        float* dst = (n0 < 256) ? out0 : out1;
        int nb = n0 & 255;
        #pragma unroll
        for (int mi = 0; mi < 4; mi++) {
            int r = m0 + warp_m * 64 + mi * 16 + g;
            #pragma unroll
            for (int ni = 0; ni < 4; ni++) {
                int n = nb + warp_n * 32 + ni * 8 + t * 2;
                *(float2*)&dst[(size_t)r * 256 + n] = make_float2(acc[mi][ni][0], acc[mi][ni][1]);
                *(float2*)&dst[(size_t)(r + 8) * 256 + n] = make_float2(acc[mi][ni][2], acc[mi][ni][3]);
            }
        }
    } else {
        int bb = m0 >> 12, l0 = m0 & 4095;
        #pragma unroll
        for (int mi = 0; mi < 4; mi++) {
            int l = l0 + warp_m * 64 + mi * 16 + g;
            #pragma unroll
            for (int ni = 0; ni < 4; ni++) {
                int ch = n0 + warp_n * 32 + ni * 8 + t * 2;
                size_t o0 = ((size_t)bb * C_ + ch) * L_ + l;
                out0[o0]          = acc[mi][ni][0] + xres[o0];
                out0[o0 + L_]     = acc[mi][ni][1] + xres[o0 + L_];
                out0[o0 + 8]      = acc[mi][ni][2] + xres[o0 + 8];
                out0[o0 + L_ + 8] = acc[mi][ni][3] + xres[o0 + L_ + 8];
            }
        }
    }
}

// ---------------- K3: conv + silu + x_proj + dt_proj + scan-phase1 ------------
__global__ void convscan_kernel(
    const float* __restrict__ cw0, const float* __restrict__ cb0,
    const float* __restrict__ xp0, const float* __restrict__ dw0, const float* __restrict__ db0,
    const float* __restrict__ Alog0,
    const float* __restrict__ cw1, const float* __restrict__ cb1,
    const float* __restrict__ xp1, const float* __restrict__ dw1, const float* __restrict__ db1,
    const float* __restrict__ Alog1) {
    extern __shared__ float sh[];
    float* su   = sh;                  // 35 x 256
    float* sxc  = su + 35 * C_;        // 32 x 256
    float* sxp  = sxc + 32 * C_;       // 24 x 256 ([o][k])
    float* sdwT = sxp + 24 * C_;       // 16 x 256 ([r][c])
    float* sdbl = sdwT + 16 * C_;      // 32 x 24

    int chk = blockIdx.x;
    int b = blockIdx.y >> 1, dir = blockIdx.y & 1;
    const float* cw = dir ? cw1 : cw0;
    const float* cb = dir ? cb1 : cb0;
    const float* xp = dir ? xp1 : xp0;
    const float* dw = dir ? dw1 : dw0;
    const float* db = dir ? db1 : db0;
    const float* Alog = dir ? Alog1 : Alog0;
    int tid = threadIdx.x;
    int q0 = chk * POS;

    for (int i = tid; i < 24 * C_; i += 256) sxp[i] = xp[i];
    for (int i = tid; i < 16 * C_; i += 256) {
        int c = i >> 4, r = i & 15;
        sdwT[r * C_ + c] = dw[i];
    }
    for (int i = tid; i < 35 * C_; i += 256) {
        int j = i >> 8, c2 = i & 255;
        int q = q0 - 3 + j;
        float v = 0.f;
        if (q >= 0) {
            int phys = dir ? (L_ - 1 - q) : q;
            v = g_u[(size_t)(b * L_ + phys) * C_ + c2];
        }
        su[j * C_ + c2] = v;
    }
    __syncthreads();

    {   // conv + silu
        int c = tid;
        float w0 = cw[c], w1 = cw[C_ + c], w2 = cw[2 * C_ + c], w3 = cw[3 * C_ + c];
        float cbv = cb[c];
        #pragma unroll
        for (int tp = 0; tp < POS; tp++) {
            float acc = cbv;
            acc = fmaf(w0, su[(tp + 0) * C_ + c], acc);
            acc = fmaf(w1, su[(tp + 1) * C_ + c], acc);
            acc = fmaf(w2, su[(tp + 2) * C_ + c], acc);
            acc = fmaf(w3, su[(tp + 3) * C_ + c], acc);
            sxc[tp * C_ + c] = siluf(acc);
        }
    }
    __syncthreads();

    {   // x_dbl
        int w = tid >> 5, ln = tid & 31;
        #pragma unroll 1
        for (int ti = 0; ti < 4; ti++) {
            int tp = w * 4 + ti;
            float xv[8];
            #pragma unroll
            for (int j = 0; j < 8; j++) xv[j] = sxc[tp * C_ + ln + 32 * j];
            #pragma unroll 1
            for (int o = 0; o < 24; o++) {
                float acc = 0.f;
                #pragma unroll
                for (int j = 0; j < 8; j++)
                    acc = fmaf(xv[j], sxp[o * C_ + ln + 32 * j], acc);
                #pragma unroll
                for (int of = 16; of; of >>= 1)
                    acc += __shfl_down_sync(0xffffffffu, acc, of);
                if (ln == 0) sdbl[tp * 24 + o] = acc;
            }
        }
    }
    __syncthreads();

    if (tid < POS * 8) {
        int pos = tid >> 3, v = tid & 7;
        g_bc[dir][(size_t)(b * L_ + q0 + pos) * 8 + v] = sdbl[pos * 24 + 16 + v];
    }

    {   // dt_proj + softplus + chunk-local summary (fp16-consistent)
        int c = tid;
        float dbv = db[c];
        float Av[4];
        #pragma unroll
        for (int n = 0; n < 4; n++) Av[n] = -__expf(Alog[c * 4 + n]);
        float h[4] = {0, 0, 0, 0}, aP[4] = {1, 1, 1, 1};
        #pragma unroll 1
        for (int pos = 0; pos < POS; pos++) {
            float val = dbv;
            #pragma unroll
            for (int r = 0; r < 16; r++)
                val = fmaf(sdbl[pos * 24 + r], sdwT[r * C_ + c], val);
            float dtv = (val > 20.f) ? val : log1pf(__expf(val));
            float uu = sxc[pos * C_ + c];
            __half2 p = __floats2half2_rn(dtv, uu);
            g_dtu[dir][(size_t)(b * L_ + q0 + pos) * C_ + c] = p;
            float2 q = __half22float2(p);
            float du = q.x * q.y;
            #pragma unroll
            for (int n = 0; n < 4; n++) {
                float a = __expf(q.x * Av[n]);
                h[n] = fmaf(a, h[n], du * sdbl[pos * 24 + 16 + n]);
                aP[n] *= a;
            }
        }
        float* cs = g_cs[dir] + ((size_t)(b * NCH + chk) * C_ + c) * 8;
        #pragma unroll
        for (int n = 0; n < 4; n++) { cs[n * 2] = aP[n]; cs[n * 2 + 1] = h[n]; }
    }
}

// ---------------- K4: scan phase 2 — coalesced serial chain per thread ---------
__global__ void scan2_kernel() {
    int tg = blockIdx.x * 256 + threadIdx.x;
    int bd = tg >> 10;
    int cn = tg & 1023;
    int b = bd >> 1, dir = bd & 1;
    const float2* cs = (const float2*)(g_cs[dir] + (size_t)b * NCH * C_ * 8) + cn;
    float* h0 = g_h0[dir] + (size_t)b * NCH * C_ * 4 + cn;
    float B = 0.f;
    #pragma unroll 8
    for (int ch = 0; ch < NCH; ch++) {
        float2 v = cs[(size_t)ch * 1024];
        h0[(size_t)ch * 1024] = B;
        B = fmaf(v.x, B, v.y);
    }
}

// ---------------- K5: fused replay(f+b) + combine + silu(z) + LN -> bf16 hi/lo -
__global__ void scan3_fused_kernel(
    const float* __restrict__ Alog0, const float* __restrict__ Alog1,
    const float* __restrict__ D0, const float* __restrict__ D1,
    const float* __restrict__ nw, const float* __restrict__ nb) {
    __shared__ float sbcf[CHK * 8], sbcb[CHK * 8];
    __shared__ float ysm[CHK * C_];
    __shared__ float smu[CHK], srs[CHK];

    int ch = blockIdx.x;
    int b  = blockIdx.y;
    int c  = threadIdx.x;
    int chb = NCH - 1 - ch;
    int l0 = ch * CHK;

    {
        const float* gf = g_bc[0] + (size_t)(b * L_ + ch * CHK) * 8;
        const float* gb = g_bc[1] + (size_t)(b * L_ + chb * CHK) * 8;
        if (c < CHK * 8) { sbcf[c] = gf[c]; sbcb[c] = gb[c]; }
    }
    __syncthreads();

    // forward replay
    {
        float Av[4];
        #pragma unroll
        for (int n = 0; n < 4; n++) Av[n] = -__expf(Alog0[c * 4 + n]);
        float Dv = D0[c];
        const float* h0p = g_h0[0] + ((size_t)(b * NCH + ch) * C_ + c) * 4;
        float h[4];
        #pragma unroll
        for (int n = 0; n < 4; n++) h[n] = h0p[n];
        const __half2* dtu = &g_dtu[0][(size_t)(b * L_ + l0) * C_ + c];
        #pragma unroll 4
        for (int t = 0; t < CHK; t++) {
            float2 v = __half22float2(dtu[(size_t)t * C_]);
            float du = v.x * v.y;
            float y = v.y * Dv;
            #pragma unroll
            for (int n = 0; n < 4; n++) {
                float a = __expf(v.x * Av[n]);
                h[n] = fmaf(a, h[n], du * sbcf[t * 8 + n]);
                y = fmaf(h[n], sbcf[t * 8 + 4 + n], y);
            }
            ysm[t * C_ + c] = y;
        }
    }
    // backward replay
    {
        float Av[4];
        #pragma unroll
        for (int n = 0; n < 4; n++) Av[n] = -__expf(Alog1[c * 4 + n]);
        float Dv = D1[c];
        const float* h0p = g_h0[1] + ((size_t)(b * NCH + chb) * C_ + c) * 4;
        float h[4];
        #pragma unroll
        for (int n = 0; n < 4; n++) h[n] = h0p[n];
        const __half2* dtu = &g_dtu[1][(size_t)(b * L_ + chb * CHK) * C_ + c];
        #pragma unroll 4
        for (int tb = 0; tb < CHK; tb++) {
            float2 v = __half22float2(dtu[(size_t)tb * C_]);
            float du = v.x * v.y;
            float y = v.y * Dv;
            #pragma unroll
            for (int n = 0; n < 4; n++) {
                float a = __expf(v.x * Av[n]);
                h[n] = fmaf(a, h[n], du * sbcb[tb * 8 + n]);
                y = fmaf(h[n], sbcb[tb * 8 + 4 + n], y);
            }
            ysm[(CHK - 1 - tb) * C_ + c] += y;
        }
    }
    // z-gate
    {
        const float* zp = &g_z[(size_t)(b * L_ + l0) * C_ + c];
        #pragma unroll 4
        for (int t = 0; t < CHK; t++) {
            float z = zp[(size_t)t * C_];
            ysm[t * C_ + c] = 0.5f * ysm[t * C_ + c] * siluf(z);
        }
    }
    __syncthreads();
    // LN stats
    {
        int w = c >> 5, ln = c & 31;
        #pragma unroll
        for (int j = 0; j < 4; j++) {
            int t = w * 4 + j;
            float sm = 0.f, sq = 0.f;
            #pragma unroll
            for (int i = 0; i < 8; i++) {
                float v = ysm[t * C_ + ln + 32 * i];
                sm += v; sq += v * v;
            }
            #pragma unroll
            for (int o = 16; o; o >>= 1) {
                sm += __shfl_down_sync(0xffffffffu, sm, o);
                sq += __shfl_down_sync(0xffffffffu, sq, o);
            }
            if (ln == 0) {
                float mu = sm * (1.f / C_);
                float var = sq * (1.f / C_) - mu * mu;
                smu[t] = mu; srs[t] = rsqrtf(var + 1e-5f);
            }
        }
    }
    __syncthreads();
    {
        float wv = nw[c], bv = nb[c];
        #pragma unroll 4
        for (int t = 0; t < CHK; t++) {
            float v = (ysm[t * C_ + c] - smu[t]) * srs[t] * wv + bv;
            __nv_bfloat16 hh = __float2bfloat16(v);
            size_t o = (size_t)(b * L_ + l0 + t) * C_ + c;
            g_ah[o] = hh;
            g_al[o] = __float2bfloat16(v - __bfloat162float(hh));
        }
    }
}

// ---------------- launch ---------------------------------------------------------
extern "C" void kernel_launch(void* const* d_in, const int* in_sizes, int n_in,
                              void* d_out, int out_size) {
    const float* x        = (const float*)d_in[0];
    const float* ln_w     = (const float*)d_in[1];
    const float* ln_b     = (const float*)d_in[2];
    const float* in_proj  = (const float*)d_in[3];
    const float* cw_f     = (const float*)d_in[4];
    const float* cb_f     = (const float*)d_in[5];
    const float* xp_f     = (const float*)d_in[6];
    const float* dw_f     = (const float*)d_in[7];
    const float* db_f     = (const float*)d_in[8];
    const float* Alog_f   = (const float*)d_in[9];
    const float* D_f      = (const float*)d_in[10];
    const float* cw_b     = (const float*)d_in[11];
    const float* cb_b     = (const float*)d_in[12];
    const float* xp_b     = (const float*)d_in[13];
    const float* dw_b     = (const float*)d_in[14];
    const float* db_b     = (const float*)d_in[15];
    const float* Alog_b   = (const float*)d_in[16];
    const float* D_b      = (const float*)d_in[17];
    const float* nrm_w    = (const float*)d_in[18];
    const float* nrm_b    = (const float*)d_in[19];
    const float* out_proj = (const float*)d_in[20];
    float* out = (float*)d_out;

    float* gu;  cudaGetSymbolAddress((void**)&gu,  g_u);
    float* gz;  cudaGetSymbolAddress((void**)&gz,  g_z);
    __nv_bfloat16 *gah, *gal, *wih, *wil, *woh, *wol;
    cudaGetSymbolAddress((void**)&gah, g_ah);
    cudaGetSymbolAddress((void**)&gal, g_al);
    cudaGetSymbolAddress((void**)&wih, g_wih);
    cudaGetSymbolAddress((void**)&wil, g_wil);
    cudaGetSymbolAddress((void**)&woh, g_woh);
    cudaGetSymbolAddress((void**)&wol, g_wol);

    const int gemm_smem = 4 * TILE_ELEM * 2;   // 73728 B
    cudaFuncSetAttribute(gemm_hmma, cudaFuncAttributeMaxDynamicSharedMemorySize, gemm_smem);
    const int conv_smem = (35 * C_ + 32 * C_ + 24 * C_ + 16 * C_ + 32 * 24) * 4;
    cudaFuncSetAttribute(convscan_kernel, cudaFuncAttributeMaxDynamicSharedMemorySize, conv_smem);

    // 0. pre-split weights to bf16 hi/lo
    wprep_kernel<<<512, 256>>>(in_proj, wih, wil, 512 * 256);
    wprep_kernel<<<256, 256>>>(out_proj, woh, wol, 256 * 256);
    // 1. LN (tiled transpose-load) -> bf16 hi/lo
    ln_kernel<<<BN_ * 128, 256>>>(x, ln_w, ln_b);
    // 2. in_proj GEMM (32768 x 512) -> u/z split
    gemm_hmma<<<dim3(4, BL_ / 128), 256, gemm_smem>>>(gah, gal, wih, wil, gu, gz, nullptr, 0);
    // 3. conv + silu + x_proj + dt_proj + scan-phase1
    convscan_kernel<<<dim3(NCH, BN_ * 2), 256, conv_smem>>>(
        cw_f, cb_f, xp_f, dw_f, db_f, Alog_f,
        cw_b, cb_b, xp_b, dw_b, db_b, Alog_b);
    // 4. scan phase 2
    scan2_kernel<<<64, 256>>>();
    // 5. fused replay + combine + silu(z) + LN -> bf16 hi/lo
    scan3_fused_kernel<<<dim3(NCH, BN_), 256>>>(Alog_f, Alog_b, D_f, D_b, nrm_w, nrm_b);
    // 6. out_proj GEMM + residual + transposed write
    gemm_hmma<<<dim3(2, BL_ / 128), 256, gemm_smem>>>(gah, gal, woh, wol, out, nullptr, x, 1);
}

// round 9
// speedup vs baseline: 5.9022x; 1.0372x over previous
#include <cuda_runtime.h>
#include <cuda_bf16.h>
#include <cuda_fp16.h>
#include <math.h>
#include <stdint.h>

#define BN_ 8
#define C_ 256
#define L_ 4096
#define BL_ (BN_*L_)
#define NCH 128
#define CHK 32
#define POS 32

// ---------------- scratch (device globals) -----------------------------------
__device__ __nv_bfloat16 g_ah[BL_*C_], g_al[BL_*C_];  // activation hi/lo
__device__ float   g_u  [BL_*C_];
__device__ float   g_z  [BL_*C_];
__device__ __half2 g_dtu[2][(size_t)BL_*C_];
__device__ float   g_bc [2][BL_*8];
__device__ float   g_cs [2][BN_*NCH*C_*8];
__device__ float   g_h0 [2][BN_*NCH*C_*4];
__device__ __nv_bfloat16 g_wih[512*256], g_wil[512*256];
__device__ __nv_bfloat16 g_woh[256*256], g_wol[256*256];

// ---------------- helpers -----------------------------------------------------
__device__ __forceinline__ float siluf(float x) { return x / (1.f + __expf(-x)); }

__device__ __forceinline__ uint32_t smem_u32(const void* p) {
    uint32_t a;
    asm("{ .reg .u64 t; cvta.to.shared.u64 t, %1; cvt.u32.u64 %0, t; }" : "=r"(a) : "l"(p));
    return a;
}

__device__ __forceinline__ void mma16816(float* c, const uint32_t* a, const uint32_t* b) {
    asm volatile(
        "mma.sync.aligned.m16n8k16.row.col.f32.bf16.bf16.f32 "
        "{%0,%1,%2,%3}, {%4,%5,%6,%7}, {%8,%9}, {%0,%1,%2,%3};"
        : "+f"(c[0]), "+f"(c[1]), "+f"(c[2]), "+f"(c[3])
        : "r"(a[0]), "r"(a[1]), "r"(a[2]), "r"(a[3]), "r"(b[0]), "r"(b[1]));
}

__device__ __forceinline__ void ldsm4(uint32_t* r, uint32_t addr) {
    asm volatile("ldmatrix.sync.aligned.m8n8.x4.shared.b16 {%0,%1,%2,%3}, [%4];"
        : "=r"(r[0]), "=r"(r[1]), "=r"(r[2]), "=r"(r[3]) : "r"(addr));
}

__device__ __forceinline__ void cpa16(uint32_t dst, const void* src) {
    asm volatile("cp.async.ca.shared.global [%0], [%1], 16;" :: "r"(dst), "l"(src));
}

// ---------------- K0: weight pre-split ------------------------------------------
__global__ void wprep_kernel(const float* __restrict__ W,
                             __nv_bfloat16* __restrict__ Wh,
                             __nv_bfloat16* __restrict__ Wl, int n) {
    int i = blockIdx.x * 256 + threadIdx.x;
    if (i < n) {
        float v = W[i];
        __nv_bfloat16 h = __float2bfloat16(v);
        Wh[i] = h;
        Wl[i] = __float2bfloat16(v - __bfloat162float(h));
    }
}

// ---------------- K1: tiled transpose + LayerNorm -> bf16 hi/lo ----------------
__global__ void ln_kernel(const float* __restrict__ x,
                          const float* __restrict__ wgt,
                          const float* __restrict__ bia) {
    __shared__ float s[C_][33];
    __shared__ float smu[32], srs[32];
    int b = blockIdx.x >> 7;
    int l0 = (blockIdx.x & 127) * 32;
    int tid = threadIdx.x, w = tid >> 5, ln = tid & 31;

    for (int c = w; c < C_; c += 8)
        s[c][ln] = x[((size_t)b * C_ + c) * L_ + l0 + ln];
    __syncthreads();

    #pragma unroll
    for (int j = 0; j < 4; j++) {
        int l = w * 4 + j;
        float sm = 0.f, sq = 0.f;
        #pragma unroll
        for (int i = 0; i < 8; i++) {
            float v = s[ln + 32 * i][l];
            sm += v; sq += v * v;
        }
        #pragma unroll
        for (int o = 16; o; o >>= 1) {
            sm += __shfl_down_sync(0xffffffffu, sm, o);
            sq += __shfl_down_sync(0xffffffffu, sq, o);
        }
        if (ln == 0) {
            float mu = sm * (1.f / C_);
            float var = sq * (1.f / C_) - mu * mu;
            smu[l] = mu; srs[l] = rsqrtf(var + 1e-5f);
        }
    }
    __syncthreads();

    int c = tid;
    float wv = wgt[c], bv = bia[c];
    for (int l = 0; l < 32; l++) {
        float v = (s[c][l] - smu[l]) * srs[l] * wv + bv;
        __nv_bfloat16 h = __float2bfloat16(v);
        size_t o = ((size_t)b * L_ + l0 + l) * C_ + c;
        g_ah[o] = h;
        g_al[o] = __float2bfloat16(v - __bfloat162float(h));
    }
}

// ---------------- K2: double-buffered cp.async split-bf16 HMMA GEMM ------------
#define SR 72
#define TILE_ELEM (128 * SR)
#define BUF_BYTES (4 * TILE_ELEM * 2)      // 73728
__global__ void __launch_bounds__(256, 1) gemm_hmma(
    const __nv_bfloat16* __restrict__ Ah, const __nv_bfloat16* __restrict__ Al,
    const __nv_bfloat16* __restrict__ Wh, const __nv_bfloat16* __restrict__ Wl,
    float* __restrict__ out0, float* __restrict__ out1,
    const float* __restrict__ xres, int mode) {
    extern __shared__ __nv_bfloat16 sm[];
    uint32_t sbase = smem_u32(sm);

    int tid = threadIdx.x, wid = tid >> 5, lid = tid & 31;
    int g = lid >> 2, t = lid & 3;
    int warp_m = wid & 1, warp_n = wid >> 1;
    int n0 = blockIdx.x * 128, m0 = blockIdx.y * 128;

    float acc[4][4][4] = {};

    int frow = tid >> 1;
    int fkh = (tid & 1) * 32;
    const __nv_bfloat16* srcs[4];
    srcs[0] = Ah + (size_t)(m0 + frow) * 256 + fkh;
    srcs[1] = Al + (size_t)(m0 + frow) * 256 + fkh;
    srcs[2] = Wh + (size_t)(n0 + frow) * 256 + fkh;
    srcs[3] = Wl + (size_t)(n0 + frow) * 256 + fkh;
    uint32_t fill_dst = sbase + (frow * SR + fkh) * 2;

    // ldmatrix per-lane byte offsets (within a buffer)
    uint32_t aoff = ((warp_m * 64 + (lid & 15)) * SR + (lid >> 4) * 8) * 2;
    int bn = (lid & 7) + ((lid >> 4) << 3);
    uint32_t boff = ((warp_n * 32 + bn) * SR + ((lid >> 3) & 1) * 8) * 2;

    // prologue: fill kc=0 (buf0), kc=1 (buf1)
    #pragma unroll
    for (int p = 0; p < 2; p++) {
        uint32_t db = fill_dst + p * BUF_BYTES;
        #pragma unroll
        for (int tno = 0; tno < 4; tno++)
            #pragma unroll
            for (int j = 0; j < 4; j++)
                cpa16(db + tno * (TILE_ELEM * 2) + j * 16, srcs[tno] + p * 64 + j * 8);
        asm volatile("cp.async.commit_group;" ::: "memory");
    }

    #pragma unroll
    for (int kc = 0; kc < 4; kc++) {
        if (kc < 3) asm volatile("cp.async.wait_group 1;" ::: "memory");
        else        asm volatile("cp.async.wait_group 0;" ::: "memory");
        __syncthreads();

        uint32_t bb = sbase + (kc & 1) * BUF_BYTES;
        uint32_t sAh_b = bb, sAl_b = bb + TILE_ELEM * 2;
        uint32_t sBh_b = bb + TILE_ELEM * 4, sBl_b = bb + TILE_ELEM * 6;

        #pragma unroll
        for (int ks = 0; ks < 4; ks++) {
            uint32_t bh[2][4], bl[2][4];
            ldsm4(bh[0], sBh_b + boff + ks * 32);
            ldsm4(bh[1], sBh_b + boff + 16 * SR * 2 + ks * 32);
            ldsm4(bl[0], sBl_b + boff + ks * 32);
            ldsm4(bl[1], sBl_b + boff + 16 * SR * 2 + ks * 32);
            #pragma unroll
            for (int mi = 0; mi < 4; mi++) {
                uint32_t ah[4], al[4];
                ldsm4(ah, sAh_b + aoff + mi * 16 * SR * 2 + ks * 32);
                ldsm4(al, sAl_b + aoff + mi * 16 * SR * 2 + ks * 32);
                #pragma unroll
                for (int ni = 0; ni < 4; ni++) {
                    const uint32_t* bph = &bh[ni >> 1][(ni & 1) * 2];
                    const uint32_t* bpl = &bl[ni >> 1][(ni & 1) * 2];
                    mma16816(acc[mi][ni], ah, bph);
                    mma16816(acc[mi][ni], ah, bpl);
                    mma16816(acc[mi][ni], al, bph);
                }
            }
        }
        __syncthreads();
        if (kc < 2) {   // fill kc+2 into buffer (kc&1)
            uint32_t db = fill_dst + (kc & 1) * BUF_BYTES;
            #pragma unroll
            for (int tno = 0; tno < 4; tno++)
                #pragma unroll
                for (int j = 0; j < 4; j++)
                    cpa16(db + tno * (TILE_ELEM * 2) + j * 16, srcs[tno] + (kc + 2) * 64 + j * 8);
            asm volatile("cp.async.commit_group;" ::: "memory");
        }
    }

    if (mode == 0) {
        float* dst = (n0 < 256) ? out0 : out1;
        int nb = n0 & 255;
        #pragma unroll
        for (int mi = 0; mi < 4; mi++) {
            int r = m0 + warp_m * 64 + mi * 16 + g;
            #pragma unroll
            for (int ni = 0; ni < 4; ni++) {
                int n = nb + warp_n * 32 + ni * 8 + t * 2;
                *(float2*)&dst[(size_t)r * 256 + n] = make_float2(acc[mi][ni][0], acc[mi][ni][1]);
                *(float2*)&dst[(size_t)(r + 8) * 256 + n] = make_float2(acc[mi][ni][2], acc[mi][ni][3]);
            }
        }
    } else {
        int bb2 = m0 >> 12, l0 = m0 & 4095;
        #pragma unroll
        for (int mi = 0; mi < 4; mi++) {
            int l = l0 + warp_m * 64 + mi * 16 + g;
            #pragma unroll
            for (int ni = 0; ni < 4; ni++) {
                int ch = n0 + warp_n * 32 + ni * 8 + t * 2;
                size_t o0 = ((size_t)bb2 * C_ + ch) * L_ + l;
                out0[o0]          = acc[mi][ni][0] + xres[o0];
                out0[o0 + L_]     = acc[mi][ni][1] + xres[o0 + L_];
                out0[o0 + 8]      = acc[mi][ni][2] + xres[o0 + 8];
                out0[o0 + L_ + 8] = acc[mi][ni][3] + xres[o0 + L_ + 8];
            }
        }
    }
}

// ---------------- K3: conv + silu + x_proj + dt_proj + scan-phase1 ------------
__global__ void convscan_kernel(
    const float* __restrict__ cw0, const float* __restrict__ cb0,
    const float* __restrict__ xp0, const float* __restrict__ dw0, const float* __restrict__ db0,
    const float* __restrict__ Alog0,
    const float* __restrict__ cw1, const float* __restrict__ cb1,
    const float* __restrict__ xp1, const float* __restrict__ dw1, const float* __restrict__ db1,
    const float* __restrict__ Alog1) {
    extern __shared__ float sh[];
    float* su   = sh;                  // 35 x 256
    float* sxc  = su + 35 * C_;        // 32 x 256
    float* sxp  = sxc + 32 * C_;       // 24 x 256 ([o][k])
    float* sdwT = sxp + 24 * C_;       // 16 x 256 ([r][c])
    float* sdbl = sdwT + 16 * C_;      // 32 x 24

    int chk = blockIdx.x;
    int b = blockIdx.y >> 1, dir = blockIdx.y & 1;
    const float* cw = dir ? cw1 : cw0;
    const float* cb = dir ? cb1 : cb0;
    const float* xp = dir ? xp1 : xp0;
    const float* dw = dir ? dw1 : dw0;
    const float* db = dir ? db1 : db0;
    const float* Alog = dir ? Alog1 : Alog0;
    int tid = threadIdx.x;
    int q0 = chk * POS;

    for (int i = tid; i < 24 * C_; i += 256) sxp[i] = xp[i];
    for (int i = tid; i < 16 * C_; i += 256) {
        int c = i >> 4, r = i & 15;
        sdwT[r * C_ + c] = dw[i];
    }
    for (int i = tid; i < 35 * C_; i += 256) {
        int j = i >> 8, c2 = i & 255;
        int q = q0 - 3 + j;
        float v = 0.f;
        if (q >= 0) {
            int phys = dir ? (L_ - 1 - q) : q;
            v = g_u[(size_t)(b * L_ + phys) * C_ + c2];
        }
        su[j * C_ + c2] = v;
    }
    __syncthreads();

    {   // conv + silu
        int c = tid;
        float w0 = cw[c], w1 = cw[C_ + c], w2 = cw[2 * C_ + c], w3 = cw[3 * C_ + c];
        float cbv = cb[c];
        #pragma unroll
        for (int tp = 0; tp < POS; tp++) {
            float acc = cbv;
            acc = fmaf(w0, su[(tp + 0) * C_ + c], acc);
            acc = fmaf(w1, su[(tp + 1) * C_ + c], acc);
            acc = fmaf(w2, su[(tp + 2) * C_ + c], acc);
            acc = fmaf(w3, su[(tp + 3) * C_ + c], acc);
            sxc[tp * C_ + c] = siluf(acc);
        }
    }
    __syncthreads();

    {   // x_dbl
        int w = tid >> 5, ln = tid & 31;
        #pragma unroll 1
        for (int ti = 0; ti < 4; ti++) {
            int tp = w * 4 + ti;
            float xv[8];
            #pragma unroll
            for (int j = 0; j < 8; j++) xv[j] = sxc[tp * C_ + ln + 32 * j];
            #pragma unroll 1
            for (int o = 0; o < 24; o++) {
                float acc = 0.f;
                #pragma unroll
                for (int j = 0; j < 8; j++)
                    acc = fmaf(xv[j], sxp[o * C_ + ln + 32 * j], acc);
                #pragma unroll
                for (int of = 16; of; of >>= 1)
                    acc += __shfl_down_sync(0xffffffffu, acc, of);
                if (ln == 0) sdbl[tp * 24 + o] = acc;
            }
        }
    }
    __syncthreads();

    if (tid < POS * 8) {
        int pos = tid >> 3, v = tid & 7;
        g_bc[dir][(size_t)(b * L_ + q0 + pos) * 8 + v] = sdbl[pos * 24 + 16 + v];
    }

    {   // dt_proj + softplus + chunk summary (fp16-consistent)
        int c = tid;
        float dbv = db[c];
        float Av[4];
        #pragma unroll
        for (int n = 0; n < 4; n++) Av[n] = -__expf(Alog[c * 4 + n]);
        float h[4] = {0, 0, 0, 0}, aP[4] = {1, 1, 1, 1};
        #pragma unroll 1
        for (int pos = 0; pos < POS; pos++) {
            float val = dbv;
            #pragma unroll
            for (int r = 0; r < 16; r++)
                val = fmaf(sdbl[pos * 24 + r], sdwT[r * C_ + c], val);
            float dtv = (val > 20.f) ? val : log1pf(__expf(val));
            float uu = sxc[pos * C_ + c];
            __half2 p = __floats2half2_rn(dtv, uu);
            g_dtu[dir][(size_t)(b * L_ + q0 + pos) * C_ + c] = p;
            float2 q = __half22float2(p);
            float du = q.x * q.y;
            #pragma unroll
            for (int n = 0; n < 4; n++) {
                float a = __expf(q.x * Av[n]);
                h[n] = fmaf(a, h[n], du * sdbl[pos * 24 + 16 + n]);
                aP[n] *= a;
            }
        }
        float* cs = g_cs[dir] + ((size_t)(b * NCH + chk) * C_ + c) * 8;
        #pragma unroll
        for (int n = 0; n < 4; n++) { cs[n * 2] = aP[n]; cs[n * 2 + 1] = h[n]; }
    }
}

// ---------------- K4: scan phase 2 ---------------------------------------------
__global__ void scan2_kernel() {
    int tg = blockIdx.x * 256 + threadIdx.x;
    int bd = tg >> 10;
    int cn = tg & 1023;
    int b = bd >> 1, dir = bd & 1;
    const float2* cs = (const float2*)(g_cs[dir] + (size_t)b * NCH * C_ * 8) + cn;
    float* h0 = g_h0[dir] + (size_t)b * NCH * C_ * 4 + cn;
    float B = 0.f;
    #pragma unroll 8
    for (int ch = 0; ch < NCH; ch++) {
        float2 v = cs[(size_t)ch * 1024];
        h0[(size_t)ch * 1024] = B;
        B = fmaf(v.x, B, v.y);
    }
}

// ---------------- K5: fused replay(f+b) + combine + silu(z) + LN ----------------
__global__ void scan3_fused_kernel(
    const float* __restrict__ Alog0, const float* __restrict__ Alog1,
    const float* __restrict__ D0, const float* __restrict__ D1,
    const float* __restrict__ nw, const float* __restrict__ nb) {
    __shared__ float sbcf[CHK * 8], sbcb[CHK * 8];
    __shared__ float ysm[CHK * C_];
    __shared__ float smu[CHK], srs[CHK];

    int ch = blockIdx.x;
    int b  = blockIdx.y;
    int c  = threadIdx.x;
    int chb = NCH - 1 - ch;
    int l0 = ch * CHK;

    {
        const float* gf = g_bc[0] + (size_t)(b * L_ + ch * CHK) * 8;
        const float* gb = g_bc[1] + (size_t)(b * L_ + chb * CHK) * 8;
        if (c < CHK * 8) { sbcf[c] = gf[c]; sbcb[c] = gb[c]; }
    }
    __syncthreads();

    // forward replay
    {
        float Av[4];
        #pragma unroll
        for (int n = 0; n < 4; n++) Av[n] = -__expf(Alog0[c * 4 + n]);
        float Dv = D0[c];
        const float* h0p = g_h0[0] + ((size_t)(b * NCH + ch) * C_ + c) * 4;
        float h[4];
        #pragma unroll
        for (int n = 0; n < 4; n++) h[n] = h0p[n];
        const __half2* dtu = &g_dtu[0][(size_t)(b * L_ + l0) * C_ + c];
        #pragma unroll 4
        for (int t = 0; t < CHK; t++) {
            float2 v = __half22float2(dtu[(size_t)t * C_]);
            float du = v.x * v.y;
            float y = v.y * Dv;
            #pragma unroll
            for (int n = 0; n < 4; n++) {
                float a = __expf(v.x * Av[n]);
                h[n] = fmaf(a, h[n], du * sbcf[t * 8 + n]);
                y = fmaf(h[n], sbcf[t * 8 + 4 + n], y);
            }
            ysm[t * C_ + c] = y;
        }
    }
    // backward replay
    {
        float Av[4];
        #pragma unroll
        for (int n = 0; n < 4; n++) Av[n] = -__expf(Alog1[c * 4 + n]);
        float Dv = D1[c];
        const float* h0p = g_h0[1] + ((size_t)(b * NCH + chb) * C_ + c) * 4;
        float h[4];
        #pragma unroll
        for (int n = 0; n < 4; n++) h[n] = h0p[n];
        const __half2* dtu = &g_dtu[1][(size_t)(b * L_ + chb * CHK) * C_ + c];
        #pragma unroll 4
        for (int tb = 0; tb < CHK; tb++) {
            float2 v = __half22float2(dtu[(size_t)tb * C_]);
            float du = v.x * v.y;
            float y = v.y * Dv;
            #pragma unroll
            for (int n = 0; n < 4; n++) {
                float a = __expf(v.x * Av[n]);
                h[n] = fmaf(a, h[n], du * sbcb[tb * 8 + n]);
                y = fmaf(h[n], sbcb[tb * 8 + 4 + n], y);
            }
            ysm[(CHK - 1 - tb) * C_ + c] += y;
        }
    }
    // z-gate
    {
        const float* zp = &g_z[(size_t)(b * L_ + l0) * C_ + c];
        #pragma unroll 4
        for (int t = 0; t < CHK; t++) {
            float z = zp[(size_t)t * C_];
            ysm[t * C_ + c] = 0.5f * ysm[t * C_ + c] * siluf(z);
        }
    }
    __syncthreads();
    // LN stats
    {
        int w = c >> 5, ln = c & 31;
        #pragma unroll
        for (int j = 0; j < 4; j++) {
            int t = w * 4 + j;
            float sm = 0.f, sq = 0.f;
            #pragma unroll
            for (int i = 0; i < 8; i++) {
                float v = ysm[t * C_ + ln + 32 * i];
                sm += v; sq += v * v;
            }
            #pragma unroll
            for (int o = 16; o; o >>= 1) {
                sm += __shfl_down_sync(0xffffffffu, sm, o);
                sq += __shfl_down_sync(0xffffffffu, sq, o);
            }
            if (ln == 0) {
                float mu = sm * (1.f / C_);
                float var = sq * (1.f / C_) - mu * mu;
                smu[t] = mu; srs[t] = rsqrtf(var + 1e-5f);
            }
        }
    }
    __syncthreads();
    {
        float wv = nw[c], bv = nb[c];
        #pragma unroll 4
        for (int t = 0; t < CHK; t++) {
            float v = (ysm[t * C_ + c] - smu[t]) * srs[t] * wv + bv;
            __nv_bfloat16 hh = __float2bfloat16(v);
            size_t o = (size_t)(b * L_ + l0 + t) * C_ + c;
            g_ah[o] = hh;
            g_al[o] = __float2bfloat16(v - __bfloat162float(hh));
        }
    }
}

// ---------------- launch ---------------------------------------------------------
extern "C" void kernel_launch(void* const* d_in, const int* in_sizes, int n_in,
                              void* d_out, int out_size) {
    const float* x        = (const float*)d_in[0];
    const float* ln_w     = (const float*)d_in[1];
    const float* ln_b     = (const float*)d_in[2];
    const float* in_proj  = (const float*)d_in[3];
    const float* cw_f     = (const float*)d_in[4];
    const float* cb_f     = (const float*)d_in[5];
    const float* xp_f     = (const float*)d_in[6];
    const float* dw_f     = (const float*)d_in[7];
    const float* db_f     = (const float*)d_in[8];
    const float* Alog_f   = (const float*)d_in[9];
    const float* D_f      = (const float*)d_in[10];
    const float* cw_b     = (const float*)d_in[11];
    const float* cb_b     = (const float*)d_in[12];
    const float* xp_b     = (const float*)d_in[13];
    const float* dw_b     = (const float*)d_in[14];
    const float* db_b     = (const float*)d_in[15];
    const float* Alog_b   = (const float*)d_in[16];
    const float* D_b      = (const float*)d_in[17];
    const float* nrm_w    = (const float*)d_in[18];
    const float* nrm_b    = (const float*)d_in[19];
    const float* out_proj = (const float*)d_in[20];
    float* out = (float*)d_out;

    float* gu;  cudaGetSymbolAddress((void**)&gu,  g_u);
    float* gz;  cudaGetSymbolAddress((void**)&gz,  g_z);
    __nv_bfloat16 *gah, *gal, *wih, *wil, *woh, *wol;
    cudaGetSymbolAddress((void**)&gah, g_ah);
    cudaGetSymbolAddress((void**)&gal, g_al);
    cudaGetSymbolAddress((void**)&wih, g_wih);
    cudaGetSymbolAddress((void**)&wil, g_wil);
    cudaGetSymbolAddress((void**)&woh, g_woh);
    cudaGetSymbolAddress((void**)&wol, g_wol);

    const int gemm_smem = 2 * BUF_BYTES;   // 147456 B
    cudaFuncSetAttribute(gemm_hmma, cudaFuncAttributeMaxDynamicSharedMemorySize, gemm_smem);
    const int conv_smem = (35 * C_ + 32 * C_ + 24 * C_ + 16 * C_ + 32 * 24) * 4;
    cudaFuncSetAttribute(convscan_kernel, cudaFuncAttributeMaxDynamicSharedMemorySize, conv_smem);

    wprep_kernel<<<512, 256>>>(in_proj, wih, wil, 512 * 256);
    wprep_kernel<<<256, 256>>>(out_proj, woh, wol, 256 * 256);
    ln_kernel<<<BN_ * 128, 256>>>(x, ln_w, ln_b);
    gemm_hmma<<<dim3(4, BL_ / 128), 256, gemm_smem>>>(gah, gal, wih, wil, gu, gz, nullptr, 0);
    convscan_kernel<<<dim3(NCH, BN_ * 2), 256, conv_smem>>>(
        cw_f, cb_f, xp_f, dw_f, db_f, Alog_f,
        cw_b, cb_b, xp_b, dw_b, db_b, Alog_b);
    scan2_kernel<<<64, 256>>>();
    scan3_fused_kernel<<<dim3(NCH, BN_), 256>>>(Alog_f, Alog_b, D_f, D_b, nrm_w, nrm_b);
    gemm_hmma<<<dim3(2, BL_ / 128), 256, gemm_smem>>>(gah, gal, woh, wol, out, nullptr, x, 1);
}